// round 5
// baseline (speedup 1.0000x reference)
#include <cuda_runtime.h>
#include <cuda_bf16.h>
#include <cstdint>

#define N_TOK 4096
#define D_MODEL 1024
#define NH 16
#define HD 64

// ---------------------------------------------------------------------------
// Scratch (__device__ globals — no allocation).
// ---------------------------------------------------------------------------
__device__ float g_Q[NH * N_TOK * HD];
__device__ float g_K[NH * N_TOK * HD];
__device__ float g_V[NH * N_TOK * HD];
__device__ __nv_bfloat16 g_x_hi[N_TOK * D_MODEL];
__device__ __nv_bfloat16 g_x_lo[N_TOK * D_MODEL];
__device__ __nv_bfloat16 g_WT_hi[4 * D_MODEL * D_MODEL];  // [which][e][k]
__device__ __nv_bfloat16 g_WT_lo[4 * D_MODEL * D_MODEL];
__device__ __nv_bfloat16 g_C_hi[NH * N_TOK * HD];          // ctx head-major
__device__ __nv_bfloat16 g_C_lo[NH * N_TOK * HD];

// HMMA m16n8k16 bf16 -> f32 accum (baseline PTX, works on sm_103 target)
__device__ __forceinline__ void mma_bf16(float* d, const uint32_t* a, const uint32_t* b) {
    asm volatile(
        "mma.sync.aligned.m16n8k16.row.col.f32.bf16.bf16.f32 "
        "{%0,%1,%2,%3}, {%4,%5,%6,%7}, {%8,%9}, {%0,%1,%2,%3};"
        : "+f"(d[0]), "+f"(d[1]), "+f"(d[2]), "+f"(d[3])
        : "r"(a[0]), "r"(a[1]), "r"(a[2]), "r"(a[3]), "r"(b[0]), "r"(b[1]));
}

// Fast exp on the FMA pipe (no MUFU). rel err ~3e-6.
__device__ __forceinline__ float fast_exp(float x) {
    float y = fmaxf(x * 1.4426950408889634f, -126.0f);
    float t = y + 12582912.0f;
    int   i = __float_as_int(t) - 0x4B400000;
    float f = y - (t - 12582912.0f);
    float p =            1.3333558146e-3f;
    p = fmaf(p, f, 9.6181291057e-3f);
    p = fmaf(p, f, 5.5504108664e-2f);
    p = fmaf(p, f, 2.4022650696e-1f);
    p = fmaf(p, f, 6.9314718056e-1f);
    p = fmaf(p, f, 1.0f);
    return __int_as_float(__float_as_int(p) + (i << 23));
}

// ---------------------------------------------------------------------------
// Prep: split x into bf16 hi/lo (K-major, same layout as x).
// ---------------------------------------------------------------------------
__global__ __launch_bounds__(256) void split_x(const float* __restrict__ x) {
    int idx = blockIdx.x * 256 + threadIdx.x;      // float4 index, 1M total
    float4 v = ((const float4*)x)[idx];
    __nv_bfloat162 h0 = __floats2bfloat162_rn(v.x, v.y);
    __nv_bfloat162 h1 = __floats2bfloat162_rn(v.z, v.w);
    float l0 = v.x - __low2float(h0), l1 = v.y - __high2float(h0);
    float l2 = v.z - __low2float(h1), l3 = v.w - __high2float(h1);
    __nv_bfloat162 e0 = __floats2bfloat162_rn(l0, l1);
    __nv_bfloat162 e1 = __floats2bfloat162_rn(l2, l3);
    ((__nv_bfloat162*)g_x_hi)[idx * 2]     = h0;
    ((__nv_bfloat162*)g_x_hi)[idx * 2 + 1] = h1;
    ((__nv_bfloat162*)g_x_lo)[idx * 2]     = e0;
    ((__nv_bfloat162*)g_x_lo)[idx * 2 + 1] = e1;
}

// ---------------------------------------------------------------------------
// Prep: WT[which][e][k] = W[k][e], split into bf16 hi/lo. 32x32 smem transpose.
// ---------------------------------------------------------------------------
__global__ void wprep(const float* __restrict__ Wq, const float* __restrict__ Wk,
                      const float* __restrict__ Wv, const float* __restrict__ Wo) {
    const int z = blockIdx.z;
    const float* W = (z == 0) ? Wq : (z == 1) ? Wk : (z == 2) ? Wv : Wo;
    __shared__ float ts[32][33];
    const int e0 = blockIdx.x * 32, k0 = blockIdx.y * 32;
    const int tx = threadIdx.x, ty = threadIdx.y;  // (32, 8)
#pragma unroll
    for (int i = 0; i < 4; i++)
        ts[ty + 8 * i][tx] = W[(size_t)(k0 + ty + 8 * i) * D_MODEL + e0 + tx];
    __syncthreads();
#pragma unroll
    for (int i = 0; i < 4; i++) {
        int row = ty + 8 * i;
        float v = ts[tx][row];
        __nv_bfloat16 hi = __float2bfloat16(v);
        float lo = v - __bfloat162float(hi);
        size_t o = (size_t)z * (D_MODEL * D_MODEL) + (size_t)(e0 + row) * D_MODEL + k0 + tx;
        g_WT_hi[o] = hi;
        g_WT_lo[o] = __float2bfloat16(lo);
    }
}

// ---------------------------------------------------------------------------
// HMMA bf16-split GEMM: D[128x128] = A[128xK] @ B^T (B = WT[e][k], K-major).
// 8 warps (2x4), 64x32 per warp, m16n8k16 fragments, K chunks of 32.
// mode 0: qkv (z picks Wq/Wk/Wv; A = x hi/lo; out scatter head-major fp32)
// mode 1: oproj (A = ctx hi/lo head-major; out = d_out + bias)
// ---------------------------------------------------------------------------
#define KC 32
#define ASTR 40  // bf16 elems per smem row (80 B: 16B-aligned, conflict-free LDS)

__global__ __launch_bounds__(256, 2) void mma_gemm(int mode, float* __restrict__ out,
                                                   const float* __restrict__ bo) {
    __shared__ __nv_bfloat16 sAh[128 * ASTR];
    __shared__ __nv_bfloat16 sAl[128 * ASTR];
    __shared__ __nv_bfloat16 sBh[128 * ASTR];
    __shared__ __nv_bfloat16 sBl[128 * ASTR];

    const int t = threadIdx.x;
    const int wid = t >> 5, lane = t & 31;
    const int wm = wid & 1, wn = wid >> 1;      // warp grid 2 x 4
    const int g = lane >> 2, tig = lane & 3;
    const int row0 = blockIdx.y * 128;
    const int col0 = blockIdx.x * 128;
    const int which = (mode == 0) ? blockIdx.z : 3;

    const __nv_bfloat16* Bh_g = g_WT_hi + (size_t)which * (D_MODEL * D_MODEL) + (size_t)col0 * D_MODEL;
    const __nv_bfloat16* Bl_g = g_WT_lo + (size_t)which * (D_MODEL * D_MODEL) + (size_t)col0 * D_MODEL;

    float acc[4][4][4] = {};   // [mt][nt][frag]

    for (int kc = 0; kc < D_MODEL / KC; kc++) {
        const int k0 = kc * KC;
        const __nv_bfloat16 *Ah_g, *Al_g;
        int astr;
        if (mode == 0) {
            Ah_g = g_x_hi + (size_t)row0 * D_MODEL + k0;
            Al_g = g_x_lo + (size_t)row0 * D_MODEL + k0;
            astr = D_MODEL;
        } else {
            size_t base = (size_t)(k0 >> 6) * (N_TOK * HD) + (size_t)row0 * HD + (k0 & 63);
            Ah_g = g_C_hi + base;
            Al_g = g_C_lo + base;
            astr = HD;
        }
        // Load chunk: 4 tiles x 512 uint4; 2 uint4 per thread per tile.
#pragma unroll
        for (int i = 0; i < 2; i++) {
            int idx = t + 256 * i;
            int r = idx >> 2, c = (idx & 3) * 8;       // 8 bf16 per uint4
            int so = r * ASTR + c;
            *(uint4*)&sAh[so] = *(const uint4*)(Ah_g + (size_t)r * astr + c);
            *(uint4*)&sAl[so] = *(const uint4*)(Al_g + (size_t)r * astr + c);
            *(uint4*)&sBh[so] = *(const uint4*)(Bh_g + (size_t)r * D_MODEL + k0 + c);
            *(uint4*)&sBl[so] = *(const uint4*)(Bl_g + (size_t)r * D_MODEL + k0 + c);
        }
        __syncthreads();

#pragma unroll
        for (int ks = 0; ks < KC; ks += 16) {
            // B fragments for all 4 n-tiles (hi + lo)
            uint32_t bh[4][2], bl[4][2];
#pragma unroll
            for (int nt = 0; nt < 4; nt++) {
                int n0 = wn * 32 + nt * 8 + g;
                bh[nt][0] = *(uint32_t*)&sBh[n0 * ASTR + ks + 2 * tig];
                bh[nt][1] = *(uint32_t*)&sBh[n0 * ASTR + ks + 8 + 2 * tig];
                bl[nt][0] = *(uint32_t*)&sBl[n0 * ASTR + ks + 2 * tig];
                bl[nt][1] = *(uint32_t*)&sBl[n0 * ASTR + ks + 8 + 2 * tig];
            }
#pragma unroll
            for (int mt = 0; mt < 4; mt++) {
                int r0 = wm * 64 + mt * 16 + g;
                uint32_t ah[4], al[4];
                ah[0] = *(uint32_t*)&sAh[r0 * ASTR + ks + 2 * tig];
                ah[1] = *(uint32_t*)&sAh[(r0 + 8) * ASTR + ks + 2 * tig];
                ah[2] = *(uint32_t*)&sAh[r0 * ASTR + ks + 8 + 2 * tig];
                ah[3] = *(uint32_t*)&sAh[(r0 + 8) * ASTR + ks + 8 + 2 * tig];
                al[0] = *(uint32_t*)&sAl[r0 * ASTR + ks + 2 * tig];
                al[1] = *(uint32_t*)&sAl[(r0 + 8) * ASTR + ks + 2 * tig];
                al[2] = *(uint32_t*)&sAl[r0 * ASTR + ks + 8 + 2 * tig];
                al[3] = *(uint32_t*)&sAl[(r0 + 8) * ASTR + ks + 8 + 2 * tig];
#pragma unroll
                for (int nt = 0; nt < 4; nt++) {
                    mma_bf16(acc[mt][nt], ah, bh[nt]);   // hi*hi
                    mma_bf16(acc[mt][nt], ah, bl[nt]);   // hi*lo
                    mma_bf16(acc[mt][nt], al, bh[nt]);   // lo*hi
                }
            }
        }
        __syncthreads();
    }

    // Epilogue: accums are (row g / g+8, cols 2tig, 2tig+1) per frag.
    if (mode == 0) {
        float* q = (which == 0) ? g_Q : (which == 1) ? g_K : g_V;
        const int head = (col0 + wn * 32) >> 6;     // constant per warp
        float* base = q + (size_t)head * (N_TOK * HD);
#pragma unroll
        for (int mt = 0; mt < 4; mt++) {
            int m = row0 + wm * 64 + mt * 16 + g;
#pragma unroll
            for (int nt = 0; nt < 4; nt++) {
                int eh = (wn * 32 + nt * 8 + 2 * tig) & 63;
                *(float2*)(base + (size_t)m * HD + eh)       = make_float2(acc[mt][nt][0], acc[mt][nt][1]);
                *(float2*)(base + (size_t)(m + 8) * HD + eh) = make_float2(acc[mt][nt][2], acc[mt][nt][3]);
            }
        }
    } else {
#pragma unroll
        for (int mt = 0; mt < 4; mt++) {
            int m = row0 + wm * 64 + mt * 16 + g;
#pragma unroll
            for (int nt = 0; nt < 4; nt++) {
                int e = col0 + wn * 32 + nt * 8 + 2 * tig;
                float2 b = *(const float2*)(bo + e);
                *(float2*)(out + (size_t)m * D_MODEL + e) =
                    make_float2(acc[mt][nt][0] + b.x, acc[mt][nt][1] + b.y);
                *(float2*)(out + (size_t)(m + 8) * D_MODEL + e) =
                    make_float2(acc[mt][nt][2] + b.x, acc[mt][nt][3] + b.y);
            }
        }
    }
}

// ---------------------------------------------------------------------------
// Causal flash attention: 128x128 tiles, poly exp, fp32 FFMA core.
// Epilogue writes ctx as bf16 hi/lo head-major for the oproj MMA.
// ---------------------------------------------------------------------------
#define QK_STR 132
#define ATTN_SMEM ((2 * 64 * QK_STR + 128 * 64 + 128 * QK_STR + 3 * 128) * 4)

__global__ __launch_bounds__(256) void attn_kernel() {
    extern __shared__ float smf[];
    float* Qs   = smf;
    float* Ks   = Qs + 64 * QK_STR;
    float* Vs   = Ks + 64 * QK_STR;
    float* Ss   = Vs + 128 * 64;
    float* m_s  = Ss + 128 * QK_STR;
    float* l_s  = m_s + 128;
    float* al_s = l_s + 128;

    const int h  = blockIdx.y;
    const int qt = (int)(gridDim.x - 1 - blockIdx.x);
    const int q0 = qt * 128;
    const float* Qg = g_Q + (size_t)h * (N_TOK * HD);
    const float* Kg = g_K + (size_t)h * (N_TOK * HD);
    const float* Vg = g_V + (size_t)h * (N_TOK * HD);

    const int t  = threadIdx.x;
    const int tx = t & 15;
    const int ty = t >> 4;
    const int dl = t & 63;
    const int tl = t >> 6;

#pragma unroll
    for (int tt = 0; tt < 128; tt += 4)
        Qs[dl * QK_STR + tt + tl] = Qg[(size_t)(q0 + tt + tl) * HD + dl];
    if (t < 128) { m_s[t] = -1e30f; l_s[t] = 0.0f; }

    int row_r[8];
#pragma unroll
    for (int i = 0; i < 8; i++) row_r[i] = (i < 4) ? (ty * 4 + i) : (64 + ty * 4 + (i - 4));
    const int colA = tx * 4;
    const int colB = 64 + tx * 4;

    float o[8][4] = {};

    for (int kt = 0; kt <= qt; kt++) {
        __syncthreads();
        const int k0 = kt * 128;
#pragma unroll
        for (int tt = 0; tt < 128; tt += 4)
            Ks[dl * QK_STR + tt + tl] = Kg[(size_t)(k0 + tt + tl) * HD + dl];
#pragma unroll
        for (int ff = 0; ff < 8; ff++) {
            int idx = t + 256 * ff;
            int r = idx >> 4, c4 = (idx & 15) * 4;
            *(float4*)&Vs[r * 64 + c4] = *(const float4*)(Vg + (size_t)(k0 + r) * HD + c4);
        }
        __syncthreads();

        float s[8][8] = {};
#pragma unroll 4
        for (int d = 0; d < HD; d++) {
            float4 a0 = *(float4*)&Qs[d * QK_STR + ty * 4];
            float4 a1 = *(float4*)&Qs[d * QK_STR + 64 + ty * 4];
            float4 b0 = *(float4*)&Ks[d * QK_STR + tx * 4];
            float4 b1 = *(float4*)&Ks[d * QK_STR + 64 + tx * 4];
            float a[8] = {a0.x, a0.y, a0.z, a0.w, a1.x, a1.y, a1.z, a1.w};
            float b[8] = {b0.x, b0.y, b0.z, b0.w, b1.x, b1.y, b1.z, b1.w};
#pragma unroll
            for (int i = 0; i < 8; i++)
#pragma unroll
                for (int j = 0; j < 8; j++) s[i][j] += a[i] * b[j];
        }

        const float scale = 0.125f;
        const bool diag = (kt == qt);
#pragma unroll
        for (int i = 0; i < 8; i++) {
            const int rg = row_r[i];
            float4 v0, v1;
            float w0[4], w1[4];
#pragma unroll
            for (int j = 0; j < 4; j++) {
                float vA = s[i][j] * scale;
                float vB = s[i][j + 4] * scale;
                if (diag && (colA + j) > rg) vA = -1e30f;
                if (diag && (colB + j) > rg) vB = -1e30f;
                w0[j] = vA; w1[j] = vB;
            }
            v0.x = w0[0]; v0.y = w0[1]; v0.z = w0[2]; v0.w = w0[3];
            v1.x = w1[0]; v1.y = w1[1]; v1.z = w1[2]; v1.w = w1[3];
            *(float4*)&Ss[rg * QK_STR + colA] = v0;
            *(float4*)&Ss[rg * QK_STR + colB] = v1;
        }
        __syncthreads();

        {
            const int row  = t >> 1;
            const int half = t & 1;
            float* Sr = Ss + row * QK_STR + half * 64;
            float mx = -1e30f;
#pragma unroll
            for (int u = 0; u < 16; u++) {
                float4 v = *(float4*)&Sr[u * 4];
                mx = fmaxf(mx, fmaxf(fmaxf(v.x, v.y), fmaxf(v.z, v.w)));
            }
            mx = fmaxf(mx, __shfl_xor_sync(0xffffffffu, mx, 1));
            float m_old = m_s[row];
            float m_new = fmaxf(m_old, mx);
            float sum = 0.0f;
#pragma unroll
            for (int u = 0; u < 16; u++) {
                float4 v = *(float4*)&Sr[u * 4];
                v.x = fast_exp(v.x - m_new);
                v.y = fast_exp(v.y - m_new);
                v.z = fast_exp(v.z - m_new);
                v.w = fast_exp(v.w - m_new);
                *(float4*)&Sr[u * 4] = v;
                sum += (v.x + v.y) + (v.z + v.w);
            }
            sum += __shfl_xor_sync(0xffffffffu, sum, 1);
            if (half == 0) {
                float alpha = fast_exp(m_old - m_new);
                l_s[row]  = l_s[row] * alpha + sum;
                m_s[row]  = m_new;
                al_s[row] = alpha;
            }
        }
        __syncthreads();

        float al[8];
#pragma unroll
        for (int i = 0; i < 8; i++) al[i] = al_s[row_r[i]];
#pragma unroll
        for (int i = 0; i < 8; i++)
#pragma unroll
            for (int j = 0; j < 4; j++) o[i][j] *= al[i];

#pragma unroll 2
        for (int k = 0; k < 128; k += 4) {
            float4 p[8];
#pragma unroll
            for (int i = 0; i < 8; i++) p[i] = *(float4*)&Ss[row_r[i] * QK_STR + k];
            float4 vv[4];
#pragma unroll
            for (int u = 0; u < 4; u++) vv[u] = *(float4*)&Vs[(k + u) * 64 + tx * 4];
#pragma unroll
            for (int i = 0; i < 8; i++) {
                float pk[4] = {p[i].x, p[i].y, p[i].z, p[i].w};
#pragma unroll
                for (int u = 0; u < 4; u++) {
                    o[i][0] = fmaf(pk[u], vv[u].x, o[i][0]);
                    o[i][1] = fmaf(pk[u], vv[u].y, o[i][1]);
                    o[i][2] = fmaf(pk[u], vv[u].z, o[i][2]);
                    o[i][3] = fmaf(pk[u], vv[u].w, o[i][3]);
                }
            }
        }
    }

    // Epilogue: normalize, split to bf16 hi/lo, write head-major.
#pragma unroll
    for (int i = 0; i < 8; i++) {
        float inv = 1.0f / l_s[row_r[i]];
        float v0 = o[i][0] * inv, v1 = o[i][1] * inv, v2 = o[i][2] * inv, v3 = o[i][3] * inv;
        __nv_bfloat162 h01 = __floats2bfloat162_rn(v0, v1);
        __nv_bfloat162 h23 = __floats2bfloat162_rn(v2, v3);
        __nv_bfloat162 l01 = __floats2bfloat162_rn(v0 - __low2float(h01), v1 - __high2float(h01));
        __nv_bfloat162 l23 = __floats2bfloat162_rn(v2 - __low2float(h23), v3 - __high2float(h23));
        size_t base = (size_t)h * (N_TOK * HD) + (size_t)(q0 + row_r[i]) * HD + tx * 4;
        ((__nv_bfloat162*)(g_C_hi + base))[0] = h01;
        ((__nv_bfloat162*)(g_C_hi + base))[1] = h23;
        ((__nv_bfloat162*)(g_C_lo + base))[0] = l01;
        ((__nv_bfloat162*)(g_C_lo + base))[1] = l23;
    }
}

extern "C" void kernel_launch(void* const* d_in, const int* in_sizes, int n_in,
                              void* d_out, int out_size) {
    const float* x  = (const float*)d_in[0];
    const float* Wq = (const float*)d_in[1];
    const float* Wk = (const float*)d_in[2];
    const float* Wv = (const float*)d_in[3];
    const float* Wo = (const float*)d_in[4];
    const float* bo = (const float*)d_in[5];
    float* out = (float*)d_out;

    cudaFuncSetAttribute(attn_kernel, cudaFuncAttributeMaxDynamicSharedMemorySize, ATTN_SMEM);

    split_x<<<(N_TOK * D_MODEL / 4) / 256, 256>>>(x);
    wprep<<<dim3(32, 32, 4), dim3(32, 8)>>>(Wq, Wk, Wv, Wo);
    mma_gemm<<<dim3(8, 32, 3), 256>>>(0, nullptr, nullptr);
    attn_kernel<<<dim3(N_TOK / 128, NH), 256, ATTN_SMEM>>>();
    mma_gemm<<<dim3(8, 32, 1), 256>>>(1, out, bo);
}

// round 6
// speedup vs baseline: 1.9048x; 1.9048x over previous
#include <cuda_runtime.h>
#include <cuda_bf16.h>
#include <cstdint>

#define N_TOK 4096
#define D_MODEL 1024
#define NH 16
#define HD 64

// ---------------------------------------------------------------------------
// Scratch (__device__ globals — no allocation).
// ---------------------------------------------------------------------------
__device__ __nv_bfloat16 g_x_hi[N_TOK * D_MODEL];
__device__ __nv_bfloat16 g_x_lo[N_TOK * D_MODEL];
__device__ __nv_bfloat16 g_WT_hi[4 * D_MODEL * D_MODEL];  // [which][e][k]
__device__ __nv_bfloat16 g_WT_lo[4 * D_MODEL * D_MODEL];
__device__ __nv_bfloat16 g_Qh[NH * N_TOK * HD];            // [h][tok][d], pre-scaled
__device__ __nv_bfloat16 g_Ql[NH * N_TOK * HD];
__device__ __nv_bfloat16 g_Kh[NH * N_TOK * HD];            // [h][tok][d]
__device__ __nv_bfloat16 g_Kl[NH * N_TOK * HD];
__device__ __nv_bfloat16 g_Vth[NH * HD * N_TOK];           // [h][d][tok] (transposed)
__device__ __nv_bfloat16 g_Vtl[NH * HD * N_TOK];
__device__ __nv_bfloat16 g_C_hi[NH * N_TOK * HD];          // ctx head-major
__device__ __nv_bfloat16 g_C_lo[NH * N_TOK * HD];

// HMMA m16n8k16 bf16 -> f32 accum (baseline PTX, works on sm_103 target)
__device__ __forceinline__ void mma_bf16(float* d, const uint32_t* a, const uint32_t* b) {
    asm volatile(
        "mma.sync.aligned.m16n8k16.row.col.f32.bf16.bf16.f32 "
        "{%0,%1,%2,%3}, {%4,%5,%6,%7}, {%8,%9}, {%0,%1,%2,%3};"
        : "+f"(d[0]), "+f"(d[1]), "+f"(d[2]), "+f"(d[3])
        : "r"(a[0]), "r"(a[1]), "r"(a[2]), "r"(a[3]), "r"(b[0]), "r"(b[1]));
}

__device__ __forceinline__ void ldsm_x4(uint32_t* r, uint32_t addr) {
    asm volatile("ldmatrix.sync.aligned.m8n8.x4.shared.b16 {%0,%1,%2,%3}, [%4];"
                 : "=r"(r[0]), "=r"(r[1]), "=r"(r[2]), "=r"(r[3]) : "r"(addr));
}

__device__ __forceinline__ uint32_t smem_u32(const void* p) {
    uint32_t a;
    asm("{ .reg .u64 t; cvta.to.shared.u64 t, %1; cvt.u32.u64 %0, t; }" : "=r"(a) : "l"(p));
    return a;
}

// Fast exp on the FMA pipe (no MUFU). rel err ~3e-6.
__device__ __forceinline__ float fast_exp(float x) {
    float y = fmaxf(x * 1.4426950408889634f, -126.0f);
    float t = y + 12582912.0f;
    int   i = __float_as_int(t) - 0x4B400000;
    float f = y - (t - 12582912.0f);
    float p =            1.3333558146e-3f;
    p = fmaf(p, f, 9.6181291057e-3f);
    p = fmaf(p, f, 5.5504108664e-2f);
    p = fmaf(p, f, 2.4022650696e-1f);
    p = fmaf(p, f, 6.9314718056e-1f);
    p = fmaf(p, f, 1.0f);
    return __int_as_float(__float_as_int(p) + (i << 23));
}

// ---------------------------------------------------------------------------
// Prep: split x into bf16 hi/lo (K-major, same layout as x).
// ---------------------------------------------------------------------------
__global__ __launch_bounds__(256) void split_x(const float* __restrict__ x) {
    int idx = blockIdx.x * 256 + threadIdx.x;
    float4 v = ((const float4*)x)[idx];
    __nv_bfloat162 h0 = __floats2bfloat162_rn(v.x, v.y);
    __nv_bfloat162 h1 = __floats2bfloat162_rn(v.z, v.w);
    float l0 = v.x - __low2float(h0), l1 = v.y - __high2float(h0);
    float l2 = v.z - __low2float(h1), l3 = v.w - __high2float(h1);
    ((__nv_bfloat162*)g_x_hi)[idx * 2]     = h0;
    ((__nv_bfloat162*)g_x_hi)[idx * 2 + 1] = h1;
    ((__nv_bfloat162*)g_x_lo)[idx * 2]     = __floats2bfloat162_rn(l0, l1);
    ((__nv_bfloat162*)g_x_lo)[idx * 2 + 1] = __floats2bfloat162_rn(l2, l3);
}

// ---------------------------------------------------------------------------
// Prep: WT[which][e][k] = W[k][e], split into bf16 hi/lo. 32x32 smem transpose.
// ---------------------------------------------------------------------------
__global__ void wprep(const float* __restrict__ Wq, const float* __restrict__ Wk,
                      const float* __restrict__ Wv, const float* __restrict__ Wo) {
    const int z = blockIdx.z;
    const float* W = (z == 0) ? Wq : (z == 1) ? Wk : (z == 2) ? Wv : Wo;
    __shared__ float ts[32][33];
    const int e0 = blockIdx.x * 32, k0 = blockIdx.y * 32;
    const int tx = threadIdx.x, ty = threadIdx.y;  // (32, 8)
#pragma unroll
    for (int i = 0; i < 4; i++)
        ts[ty + 8 * i][tx] = W[(size_t)(k0 + ty + 8 * i) * D_MODEL + e0 + tx];
    __syncthreads();
#pragma unroll
    for (int i = 0; i < 4; i++) {
        int row = ty + 8 * i;
        float v = ts[tx][row];
        __nv_bfloat16 hi = __float2bfloat16(v);
        float lo = v - __bfloat162float(hi);
        size_t o = (size_t)z * (D_MODEL * D_MODEL) + (size_t)(e0 + row) * D_MODEL + k0 + tx;
        g_WT_hi[o] = hi;
        g_WT_lo[o] = __float2bfloat16(lo);
    }
}

// ---------------------------------------------------------------------------
// HMMA bf16-split GEMM: D[128x128] = A[128xK] @ B^T (B = WT[e][k], K-major).
// mode 0: qkv — epilogue splits to bf16 hi/lo: Q (scaled 1/8) & K row-major,
//         V transposed [h][d][tok].
// mode 1: oproj (A = ctx hi/lo head-major; out = d_out + bias, fp32)
// ---------------------------------------------------------------------------
#define KC 32
#define ASTR 40

__global__ __launch_bounds__(256, 2) void mma_gemm(int mode, float* __restrict__ out,
                                                   const float* __restrict__ bo) {
    __shared__ __nv_bfloat16 sAh[128 * ASTR];
    __shared__ __nv_bfloat16 sAl[128 * ASTR];
    __shared__ __nv_bfloat16 sBh[128 * ASTR];
    __shared__ __nv_bfloat16 sBl[128 * ASTR];

    const int t = threadIdx.x;
    const int wid = t >> 5, lane = t & 31;
    const int wm = wid & 1, wn = wid >> 1;
    const int g = lane >> 2, tig = lane & 3;
    const int row0 = blockIdx.y * 128;
    const int col0 = blockIdx.x * 128;
    const int which = (mode == 0) ? blockIdx.z : 3;

    const __nv_bfloat16* Bh_g = g_WT_hi + (size_t)which * (D_MODEL * D_MODEL) + (size_t)col0 * D_MODEL;
    const __nv_bfloat16* Bl_g = g_WT_lo + (size_t)which * (D_MODEL * D_MODEL) + (size_t)col0 * D_MODEL;

    float acc[4][4][4] = {};

    for (int kc = 0; kc < D_MODEL / KC; kc++) {
        const int k0 = kc * KC;
        const __nv_bfloat16 *Ah_g, *Al_g;
        int astr;
        if (mode == 0) {
            Ah_g = g_x_hi + (size_t)row0 * D_MODEL + k0;
            Al_g = g_x_lo + (size_t)row0 * D_MODEL + k0;
            astr = D_MODEL;
        } else {
            size_t base = (size_t)(k0 >> 6) * (N_TOK * HD) + (size_t)row0 * HD + (k0 & 63);
            Ah_g = g_C_hi + base;
            Al_g = g_C_lo + base;
            astr = HD;
        }
#pragma unroll
        for (int i = 0; i < 2; i++) {
            int idx = t + 256 * i;
            int r = idx >> 2, c = (idx & 3) * 8;
            int so = r * ASTR + c;
            *(uint4*)&sAh[so] = *(const uint4*)(Ah_g + (size_t)r * astr + c);
            *(uint4*)&sAl[so] = *(const uint4*)(Al_g + (size_t)r * astr + c);
            *(uint4*)&sBh[so] = *(const uint4*)(Bh_g + (size_t)r * D_MODEL + k0 + c);
            *(uint4*)&sBl[so] = *(const uint4*)(Bl_g + (size_t)r * D_MODEL + k0 + c);
        }
        __syncthreads();

#pragma unroll
        for (int ks = 0; ks < KC; ks += 16) {
            uint32_t bh[4][2], bl[4][2];
#pragma unroll
            for (int nt = 0; nt < 4; nt++) {
                int n0 = wn * 32 + nt * 8 + g;
                bh[nt][0] = *(uint32_t*)&sBh[n0 * ASTR + ks + 2 * tig];
                bh[nt][1] = *(uint32_t*)&sBh[n0 * ASTR + ks + 8 + 2 * tig];
                bl[nt][0] = *(uint32_t*)&sBl[n0 * ASTR + ks + 2 * tig];
                bl[nt][1] = *(uint32_t*)&sBl[n0 * ASTR + ks + 8 + 2 * tig];
            }
#pragma unroll
            for (int mt = 0; mt < 4; mt++) {
                int r0 = wm * 64 + mt * 16 + g;
                uint32_t ah[4], al[4];
                ah[0] = *(uint32_t*)&sAh[r0 * ASTR + ks + 2 * tig];
                ah[1] = *(uint32_t*)&sAh[(r0 + 8) * ASTR + ks + 2 * tig];
                ah[2] = *(uint32_t*)&sAh[r0 * ASTR + ks + 8 + 2 * tig];
                ah[3] = *(uint32_t*)&sAh[(r0 + 8) * ASTR + ks + 8 + 2 * tig];
                al[0] = *(uint32_t*)&sAl[r0 * ASTR + ks + 2 * tig];
                al[1] = *(uint32_t*)&sAl[(r0 + 8) * ASTR + ks + 2 * tig];
                al[2] = *(uint32_t*)&sAl[r0 * ASTR + ks + 8 + 2 * tig];
                al[3] = *(uint32_t*)&sAl[(r0 + 8) * ASTR + ks + 8 + 2 * tig];
#pragma unroll
                for (int nt = 0; nt < 4; nt++) {
                    mma_bf16(acc[mt][nt], ah, bh[nt]);
                    mma_bf16(acc[mt][nt], ah, bl[nt]);
                    mma_bf16(acc[mt][nt], al, bh[nt]);
                }
            }
        }
        __syncthreads();
    }

    if (mode == 0) {
        const int head = (col0 + wn * 32) >> 6;
        const float sc = (which == 0) ? 0.125f : 1.0f;   // fold 1/sqrt(64) into Q
#pragma unroll
        for (int mt = 0; mt < 4; mt++) {
            int m = row0 + wm * 64 + mt * 16 + g;
#pragma unroll
            for (int nt = 0; nt < 4; nt++) {
                int eh = (wn * 32 + nt * 8 + 2 * tig) & 63;
                float v00 = acc[mt][nt][0] * sc, v01 = acc[mt][nt][1] * sc;
                float v10 = acc[mt][nt][2] * sc, v11 = acc[mt][nt][3] * sc;
                __nv_bfloat162 h0 = __floats2bfloat162_rn(v00, v01);
                __nv_bfloat162 h1 = __floats2bfloat162_rn(v10, v11);
                __nv_bfloat162 l0 = __floats2bfloat162_rn(v00 - __low2float(h0), v01 - __high2float(h0));
                __nv_bfloat162 l1 = __floats2bfloat162_rn(v10 - __low2float(h1), v11 - __high2float(h1));
                if (which == 2) {
                    size_t vb = (size_t)head * (HD * N_TOK);
                    g_Vth[vb + (size_t)eh * N_TOK + m]           = h0.x;
                    g_Vth[vb + (size_t)(eh + 1) * N_TOK + m]     = h0.y;
                    g_Vth[vb + (size_t)eh * N_TOK + m + 8]       = h1.x;
                    g_Vth[vb + (size_t)(eh + 1) * N_TOK + m + 8] = h1.y;
                    g_Vtl[vb + (size_t)eh * N_TOK + m]           = l0.x;
                    g_Vtl[vb + (size_t)(eh + 1) * N_TOK + m]     = l0.y;
                    g_Vtl[vb + (size_t)eh * N_TOK + m + 8]       = l1.x;
                    g_Vtl[vb + (size_t)(eh + 1) * N_TOK + m + 8] = l1.y;
                } else {
                    __nv_bfloat16* dh = (which == 0) ? g_Qh : g_Kh;
                    __nv_bfloat16* dl = (which == 0) ? g_Ql : g_Kl;
                    size_t b0 = (size_t)head * (N_TOK * HD) + (size_t)m * HD + eh;
                    size_t b1 = b0 + 8 * HD;
                    *(__nv_bfloat162*)(dh + b0) = h0;
                    *(__nv_bfloat162*)(dh + b1) = h1;
                    *(__nv_bfloat162*)(dl + b0) = l0;
                    *(__nv_bfloat162*)(dl + b1) = l1;
                }
            }
        }
    } else {
#pragma unroll
        for (int mt = 0; mt < 4; mt++) {
            int m = row0 + wm * 64 + mt * 16 + g;
#pragma unroll
            for (int nt = 0; nt < 4; nt++) {
                int e = col0 + wn * 32 + nt * 8 + 2 * tig;
                float2 b = *(const float2*)(bo + e);
                *(float2*)(out + (size_t)m * D_MODEL + e) =
                    make_float2(acc[mt][nt][0] + b.x, acc[mt][nt][1] + b.y);
                *(float2*)(out + (size_t)(m + 8) * D_MODEL + e) =
                    make_float2(acc[mt][nt][2] + b.x, acc[mt][nt][3] + b.y);
            }
        }
    }
}

// ---------------------------------------------------------------------------
// Tensor-core causal flash attention. CTA = 128 q x 128 k, 8 warps x 16 rows.
// S and softmax fully in registers; K/Vt staged in smem, ldmatrix.x4 B-frags.
// ---------------------------------------------------------------------------
#define AT_KSTR 72    // K smem row stride (bf16): 8 rows cover all 32 banks
#define AT_VSTR 136   // Vt smem row stride (bf16)
#define AT_SMEM ((2 * 128 * AT_KSTR + 2 * 64 * AT_VSTR) * 2)  // 71680 B

__global__ __launch_bounds__(256, 1) void attn_mma() {
    extern __shared__ __nv_bfloat16 sb[];
    __nv_bfloat16* sKh = sb;
    __nv_bfloat16* sKl = sKh + 128 * AT_KSTR;
    __nv_bfloat16* sVh = sKl + 128 * AT_KSTR;
    __nv_bfloat16* sVl = sVh + 64 * AT_VSTR;

    const int h  = blockIdx.y;
    const int qt = (int)(gridDim.x - 1 - blockIdx.x);  // big tiles first
    const int q0 = qt * 128;
    const int t = threadIdx.x, wid = t >> 5, lane = t & 31;
    const int g = lane >> 2, tig = lane & 3;

    const __nv_bfloat16* Qh_g = g_Qh + (size_t)h * (N_TOK * HD);
    const __nv_bfloat16* Ql_g = g_Ql + (size_t)h * (N_TOK * HD);
    const __nv_bfloat16* Kh_g = g_Kh + (size_t)h * (N_TOK * HD);
    const __nv_bfloat16* Kl_g = g_Kl + (size_t)h * (N_TOK * HD);
    const __nv_bfloat16* Vh_g = g_Vth + (size_t)h * (HD * N_TOK);
    const __nv_bfloat16* Vl_g = g_Vtl + (size_t)h * (HD * N_TOK);

    const int qrow = q0 + wid * 16 + g;   // this thread's first row

    // Preload Q fragments (already scaled by 1/8 at projection time)
    uint32_t qfh[4][4], qfl[4][4];
#pragma unroll
    for (int ks = 0; ks < 4; ks++) {
        int c = ks * 16 + 2 * tig;
        qfh[ks][0] = *(const uint32_t*)(Qh_g + (size_t)qrow * HD + c);
        qfh[ks][1] = *(const uint32_t*)(Qh_g + (size_t)(qrow + 8) * HD + c);
        qfh[ks][2] = *(const uint32_t*)(Qh_g + (size_t)qrow * HD + c + 8);
        qfh[ks][3] = *(const uint32_t*)(Qh_g + (size_t)(qrow + 8) * HD + c + 8);
        qfl[ks][0] = *(const uint32_t*)(Ql_g + (size_t)qrow * HD + c);
        qfl[ks][1] = *(const uint32_t*)(Ql_g + (size_t)(qrow + 8) * HD + c);
        qfl[ks][2] = *(const uint32_t*)(Ql_g + (size_t)qrow * HD + c + 8);
        qfl[ks][3] = *(const uint32_t*)(Ql_g + (size_t)(qrow + 8) * HD + c + 8);
    }

    // ldmatrix lane offsets: tiles (rows r0..r0+7 / +8) x (col base, +8)
    const int rofs = (lane & 7) + ((lane & 16) >> 1);
    const int cofs = (lane & 8);
    const uint32_t kb_h = smem_u32(sKh) + (uint32_t)(rofs * AT_KSTR + cofs) * 2;
    const uint32_t kb_l = smem_u32(sKl) + (uint32_t)(rofs * AT_KSTR + cofs) * 2;
    const uint32_t vb_h = smem_u32(sVh) + (uint32_t)(rofs * AT_VSTR + cofs) * 2;
    const uint32_t vb_l = smem_u32(sVl) + (uint32_t)(rofs * AT_VSTR + cofs) * 2;

    float m0 = -1e30f, m1 = -1e30f, l0 = 0.0f, l1 = 0.0f;
    float o[8][4] = {};

    for (int kt = 0; kt <= qt; kt++) {
        __syncthreads();
        const int k0 = kt * 128;
#pragma unroll
        for (int i = 0; i < 4; i++) {
            int idx = t + 256 * i;
            int r = idx >> 3, c8 = (idx & 7) * 8;
            *(uint4*)&sKh[r * AT_KSTR + c8] = *(const uint4*)(Kh_g + (size_t)(k0 + r) * HD + c8);
            *(uint4*)&sKl[r * AT_KSTR + c8] = *(const uint4*)(Kl_g + (size_t)(k0 + r) * HD + c8);
        }
#pragma unroll
        for (int i = 0; i < 4; i++) {
            int idx = t + 256 * i;
            int r = idx >> 4, c8 = (idx & 15) * 8;
            *(uint4*)&sVh[r * AT_VSTR + c8] = *(const uint4*)(Vh_g + (size_t)r * N_TOK + k0 + c8);
            *(uint4*)&sVl[r * AT_VSTR + c8] = *(const uint4*)(Vl_g + (size_t)r * N_TOK + k0 + c8);
        }
        __syncthreads();

        // S = Q K^T  (16 n-frags x 4 floats per thread)
        float s[16][4];
#pragma unroll
        for (int nt = 0; nt < 16; nt++) { s[nt][0] = s[nt][1] = s[nt][2] = s[nt][3] = 0.0f; }
#pragma unroll
        for (int ks = 0; ks < 4; ks++) {
#pragma unroll
            for (int ntp = 0; ntp < 8; ntp++) {
                uint32_t bh[4], bl[4];
                uint32_t off = (uint32_t)(ntp * 16 * AT_KSTR + ks * 16) * 2;
                ldsm_x4(bh, kb_h + off);
                ldsm_x4(bl, kb_l + off);
                mma_bf16(s[2 * ntp],     qfh[ks], bh);
                mma_bf16(s[2 * ntp],     qfh[ks], bl);
                mma_bf16(s[2 * ntp],     qfl[ks], bh);
                mma_bf16(s[2 * ntp + 1], qfh[ks], bh + 2);
                mma_bf16(s[2 * ntp + 1], qfh[ks], bl + 2);
                mma_bf16(s[2 * ntp + 1], qfl[ks], bh + 2);
            }
        }

        if (kt == qt) {   // causal mask on diagonal tile
#pragma unroll
            for (int nt = 0; nt < 16; nt++) {
                int c = k0 + nt * 8 + 2 * tig;
                if (c     > qrow)     s[nt][0] = -1e30f;
                if (c + 1 > qrow)     s[nt][1] = -1e30f;
                if (c     > qrow + 8) s[nt][2] = -1e30f;
                if (c + 1 > qrow + 8) s[nt][3] = -1e30f;
            }
        }

        // Online softmax (registers + shfl over the 4 tig lanes)
        float mx0 = -1e30f, mx1 = -1e30f;
#pragma unroll
        for (int nt = 0; nt < 16; nt++) {
            mx0 = fmaxf(mx0, fmaxf(s[nt][0], s[nt][1]));
            mx1 = fmaxf(mx1, fmaxf(s[nt][2], s[nt][3]));
        }
        mx0 = fmaxf(mx0, __shfl_xor_sync(0xffffffffu, mx0, 1));
        mx0 = fmaxf(mx0, __shfl_xor_sync(0xffffffffu, mx0, 2));
        mx1 = fmaxf(mx1, __shfl_xor_sync(0xffffffffu, mx1, 1));
        mx1 = fmaxf(mx1, __shfl_xor_sync(0xffffffffu, mx1, 2));
        float mn0 = fmaxf(m0, mx0), mn1 = fmaxf(m1, mx1);
        float a0 = fast_exp(m0 - mn0), a1 = fast_exp(m1 - mn1);
        m0 = mn0; m1 = mn1;
        float sum0 = 0.0f, sum1 = 0.0f;
#pragma unroll
        for (int nt = 0; nt < 16; nt++) {
            s[nt][0] = fast_exp(s[nt][0] - mn0);
            s[nt][1] = fast_exp(s[nt][1] - mn0);
            s[nt][2] = fast_exp(s[nt][2] - mn1);
            s[nt][3] = fast_exp(s[nt][3] - mn1);
            sum0 += s[nt][0] + s[nt][1];
            sum1 += s[nt][2] + s[nt][3];
        }
        sum0 += __shfl_xor_sync(0xffffffffu, sum0, 1);
        sum0 += __shfl_xor_sync(0xffffffffu, sum0, 2);
        sum1 += __shfl_xor_sync(0xffffffffu, sum1, 1);
        sum1 += __shfl_xor_sync(0xffffffffu, sum1, 2);
        l0 = l0 * a0 + sum0;
        l1 = l1 * a1 + sum1;
#pragma unroll
        for (int f = 0; f < 8; f++) {
            o[f][0] *= a0; o[f][1] *= a0; o[f][2] *= a1; o[f][3] *= a1;
        }

        // O += P V  (P split hi/lo in registers; V from smem via ldmatrix)
#pragma unroll
        for (int kk = 0; kk < 8; kk++) {
            uint32_t ph[4], pl[4];
            {
                __nv_bfloat162 t0 = __floats2bfloat162_rn(s[2 * kk][0], s[2 * kk][1]);
                __nv_bfloat162 t1 = __floats2bfloat162_rn(s[2 * kk][2], s[2 * kk][3]);
                __nv_bfloat162 t2 = __floats2bfloat162_rn(s[2 * kk + 1][0], s[2 * kk + 1][1]);
                __nv_bfloat162 t3 = __floats2bfloat162_rn(s[2 * kk + 1][2], s[2 * kk + 1][3]);
                ph[0] = *(uint32_t*)&t0; ph[1] = *(uint32_t*)&t1;
                ph[2] = *(uint32_t*)&t2; ph[3] = *(uint32_t*)&t3;
                __nv_bfloat162 u0 = __floats2bfloat162_rn(s[2 * kk][0] - __low2float(t0),
                                                          s[2 * kk][1] - __high2float(t0));
                __nv_bfloat162 u1 = __floats2bfloat162_rn(s[2 * kk][2] - __low2float(t1),
                                                          s[2 * kk][3] - __high2float(t1));
                __nv_bfloat162 u2 = __floats2bfloat162_rn(s[2 * kk + 1][0] - __low2float(t2),
                                                          s[2 * kk + 1][1] - __high2float(t2));
                __nv_bfloat162 u3 = __floats2bfloat162_rn(s[2 * kk + 1][2] - __low2float(t3),
                                                          s[2 * kk + 1][3] - __high2float(t3));
                pl[0] = *(uint32_t*)&u0; pl[1] = *(uint32_t*)&u1;
                pl[2] = *(uint32_t*)&u2; pl[3] = *(uint32_t*)&u3;
            }
#pragma unroll
            for (int dtp = 0; dtp < 4; dtp++) {
                uint32_t bh[4], bl[4];
                uint32_t off = (uint32_t)(dtp * 16 * AT_VSTR + kk * 16) * 2;
                ldsm_x4(bh, vb_h + off);
                ldsm_x4(bl, vb_l + off);
                mma_bf16(o[2 * dtp],     ph, bh);
                mma_bf16(o[2 * dtp],     ph, bl);
                mma_bf16(o[2 * dtp],     pl, bh);
                mma_bf16(o[2 * dtp + 1], ph, bh + 2);
                mma_bf16(o[2 * dtp + 1], ph, bl + 2);
                mma_bf16(o[2 * dtp + 1], pl, bh + 2);
            }
        }
    }

    // Epilogue: normalize, split to bf16 hi/lo, write ctx head-major.
    float i0 = 1.0f / l0, i1 = 1.0f / l1;
#pragma unroll
    for (int f = 0; f < 8; f++) {
        int d = f * 8 + 2 * tig;
        float v00 = o[f][0] * i0, v01 = o[f][1] * i0;
        float v10 = o[f][2] * i1, v11 = o[f][3] * i1;
        __nv_bfloat162 h0 = __floats2bfloat162_rn(v00, v01);
        __nv_bfloat162 h1 = __floats2bfloat162_rn(v10, v11);
        __nv_bfloat162 e0 = __floats2bfloat162_rn(v00 - __low2float(h0), v01 - __high2float(h0));
        __nv_bfloat162 e1 = __floats2bfloat162_rn(v10 - __low2float(h1), v11 - __high2float(h1));
        size_t b0 = (size_t)h * (N_TOK * HD) + (size_t)qrow * HD + d;
        size_t b1 = b0 + 8 * HD;
        *(__nv_bfloat162*)(g_C_hi + b0) = h0;
        *(__nv_bfloat162*)(g_C_hi + b1) = h1;
        *(__nv_bfloat162*)(g_C_lo + b0) = e0;
        *(__nv_bfloat162*)(g_C_lo + b1) = e1;
    }
}

extern "C" void kernel_launch(void* const* d_in, const int* in_sizes, int n_in,
                              void* d_out, int out_size) {
    const float* x  = (const float*)d_in[0];
    const float* Wq = (const float*)d_in[1];
    const float* Wk = (const float*)d_in[2];
    const float* Wv = (const float*)d_in[3];
    const float* Wo = (const float*)d_in[4];
    const float* bo = (const float*)d_in[5];
    float* out = (float*)d_out;

    cudaFuncSetAttribute(attn_mma, cudaFuncAttributeMaxDynamicSharedMemorySize, AT_SMEM);

    split_x<<<(N_TOK * D_MODEL / 4) / 256, 256>>>(x);
    wprep<<<dim3(32, 32, 4), dim3(32, 8)>>>(Wq, Wk, Wv, Wo);
    mma_gemm<<<dim3(8, 32, 3), 256>>>(0, nullptr, nullptr);
    attn_mma<<<dim3(N_TOK / 128, NH), 256, AT_SMEM>>>();
    mma_gemm<<<dim3(8, 32, 1), 256>>>(1, out, bo);
}

// round 7
// speedup vs baseline: 2.0575x; 1.0802x over previous
#include <cuda_runtime.h>
#include <cuda_bf16.h>
#include <cstdint>

#define N_TOK 4096
#define D_MODEL 1024
#define NH 16
#define HD 64

// ---------------------------------------------------------------------------
// Scratch (__device__ globals — no allocation).
// ---------------------------------------------------------------------------
__device__ __nv_bfloat16 g_x_hi[N_TOK * D_MODEL];
__device__ __nv_bfloat16 g_x_lo[N_TOK * D_MODEL];
__device__ __nv_bfloat16 g_WT_hi[4 * D_MODEL * D_MODEL];  // [which][e][k]
__device__ __nv_bfloat16 g_WT_lo[4 * D_MODEL * D_MODEL];
__device__ __nv_bfloat16 g_Qh[NH * N_TOK * HD];            // [h][tok][d], scaled log2e/8
__device__ __nv_bfloat16 g_Ql[NH * N_TOK * HD];
__device__ __nv_bfloat16 g_Kh[NH * N_TOK * HD];            // [h][tok][d]
__device__ __nv_bfloat16 g_Kl[NH * N_TOK * HD];
__device__ __nv_bfloat16 g_Vth[NH * HD * N_TOK];           // [h][d][tok] (transposed)
__device__ __nv_bfloat16 g_Vtl[NH * HD * N_TOK];
__device__ __nv_bfloat16 g_C_hi[NH * N_TOK * HD];          // ctx head-major
__device__ __nv_bfloat16 g_C_lo[NH * N_TOK * HD];

// HMMA m16n8k16 bf16 -> f32 accum (baseline PTX, works on sm_103 target)
__device__ __forceinline__ void mma_bf16(float* d, const uint32_t* a, const uint32_t* b) {
    asm volatile(
        "mma.sync.aligned.m16n8k16.row.col.f32.bf16.bf16.f32 "
        "{%0,%1,%2,%3}, {%4,%5,%6,%7}, {%8,%9}, {%0,%1,%2,%3};"
        : "+f"(d[0]), "+f"(d[1]), "+f"(d[2]), "+f"(d[3])
        : "r"(a[0]), "r"(a[1]), "r"(a[2]), "r"(a[3]), "r"(b[0]), "r"(b[1]));
}

__device__ __forceinline__ void ldsm_x4(uint32_t* r, uint32_t addr) {
    asm volatile("ldmatrix.sync.aligned.m8n8.x4.shared.b16 {%0,%1,%2,%3}, [%4];"
                 : "=r"(r[0]), "=r"(r[1]), "=r"(r[2]), "=r"(r[3]) : "r"(addr));
}

__device__ __forceinline__ uint32_t smem_u32(const void* p) {
    uint32_t a;
    asm("{ .reg .u64 t; cvta.to.shared.u64 t, %1; cvt.u32.u64 %0, t; }" : "=r"(a) : "l"(p));
    return a;
}

__device__ __forceinline__ void cp16(uint32_t saddr, const void* g) {
    asm volatile("cp.async.cg.shared.global [%0], [%1], 16;" :: "r"(saddr), "l"(g));
}
#define CP_COMMIT() asm volatile("cp.async.commit_group;" ::: "memory")
#define CP_WAIT0()  asm volatile("cp.async.wait_group 0;" ::: "memory")

// Fast 2^y on the FMA pipe (no MUFU). rel err ~3e-6.
__device__ __forceinline__ float fast_exp2(float y) {
    y = fmaxf(y, -126.0f);
    float t = y + 12582912.0f;                       // 1.5 * 2^23
    int   i = __float_as_int(t) - 0x4B400000;
    float f = y - (t - 12582912.0f);                 // f in [-0.5, 0.5]
    float p =            1.3333558146e-3f;
    p = fmaf(p, f, 9.6181291057e-3f);
    p = fmaf(p, f, 5.5504108664e-2f);
    p = fmaf(p, f, 2.4022650696e-1f);
    p = fmaf(p, f, 6.9314718056e-1f);
    p = fmaf(p, f, 1.0f);
    return __int_as_float(__float_as_int(p) + (i << 23));
}

// ---------------------------------------------------------------------------
// Prep: split x into bf16 hi/lo (K-major, same layout as x).
// ---------------------------------------------------------------------------
__global__ __launch_bounds__(256) void split_x(const float* __restrict__ x) {
    int idx = blockIdx.x * 256 + threadIdx.x;
    float4 v = ((const float4*)x)[idx];
    __nv_bfloat162 h0 = __floats2bfloat162_rn(v.x, v.y);
    __nv_bfloat162 h1 = __floats2bfloat162_rn(v.z, v.w);
    float l0 = v.x - __low2float(h0), l1 = v.y - __high2float(h0);
    float l2 = v.z - __low2float(h1), l3 = v.w - __high2float(h1);
    ((__nv_bfloat162*)g_x_hi)[idx * 2]     = h0;
    ((__nv_bfloat162*)g_x_hi)[idx * 2 + 1] = h1;
    ((__nv_bfloat162*)g_x_lo)[idx * 2]     = __floats2bfloat162_rn(l0, l1);
    ((__nv_bfloat162*)g_x_lo)[idx * 2 + 1] = __floats2bfloat162_rn(l2, l3);
}

// ---------------------------------------------------------------------------
// Prep: WT[which][e][k] = W[k][e], split into bf16 hi/lo. 32x32 smem transpose.
// ---------------------------------------------------------------------------
__global__ void wprep(const float* __restrict__ Wq, const float* __restrict__ Wk,
                      const float* __restrict__ Wv, const float* __restrict__ Wo) {
    const int z = blockIdx.z;
    const float* W = (z == 0) ? Wq : (z == 1) ? Wk : (z == 2) ? Wv : Wo;
    __shared__ float ts[32][33];
    const int e0 = blockIdx.x * 32, k0 = blockIdx.y * 32;
    const int tx = threadIdx.x, ty = threadIdx.y;  // (32, 8)
#pragma unroll
    for (int i = 0; i < 4; i++)
        ts[ty + 8 * i][tx] = W[(size_t)(k0 + ty + 8 * i) * D_MODEL + e0 + tx];
    __syncthreads();
#pragma unroll
    for (int i = 0; i < 4; i++) {
        int row = ty + 8 * i;
        float v = ts[tx][row];
        __nv_bfloat16 hi = __float2bfloat16(v);
        float lo = v - __bfloat162float(hi);
        size_t o = (size_t)z * (D_MODEL * D_MODEL) + (size_t)(e0 + row) * D_MODEL + k0 + tx;
        g_WT_hi[o] = hi;
        g_WT_lo[o] = __float2bfloat16(lo);
    }
}

// ---------------------------------------------------------------------------
// HMMA bf16-split GEMM, cp.async double-buffered K chunks.
// mode 0: qkv — epilogue splits hi/lo: Q (scaled log2e/8) & K row-major,
//         V transposed [h][d][tok].
// mode 1: oproj (A = ctx hi/lo head-major; out = d_out + bias, fp32)
// ---------------------------------------------------------------------------
#define KC 32
#define ASTR 40
#define G_TILE  (128 * ASTR * 2)        // 10240 B per tile
#define G_STAGE (4 * G_TILE)            // 40960 B per stage
#define G_SMEM  (2 * G_STAGE)           // 81920 B

__global__ __launch_bounds__(256, 2) void mma_gemm(int mode, float* __restrict__ out,
                                                   const float* __restrict__ bo) {
    extern __shared__ char smc[];
    const uint32_t sbase = smem_u32(smc);

    const int t = threadIdx.x;
    const int wid = t >> 5, lane = t & 31;
    const int wm = wid & 1, wn = wid >> 1;
    const int g = lane >> 2, tig = lane & 3;
    const int row0 = blockIdx.y * 128;
    const int col0 = blockIdx.x * 128;
    const int which = (mode == 0) ? blockIdx.z : 3;

    const __nv_bfloat16* Bh_g = g_WT_hi + (size_t)which * (D_MODEL * D_MODEL) + (size_t)col0 * D_MODEL;
    const __nv_bfloat16* Bl_g = g_WT_lo + (size_t)which * (D_MODEL * D_MODEL) + (size_t)col0 * D_MODEL;

    const int ld_r = t >> 2, ld_c = (t & 3) * 8;     // each thread: 2 rows x 8 bf16

    auto issue_chunk = [&](int kc) {
        const int k0 = kc * KC;
        const __nv_bfloat16 *Ah_g, *Al_g;
        int astr;
        if (mode == 0) {
            Ah_g = g_x_hi + (size_t)row0 * D_MODEL + k0;
            Al_g = g_x_lo + (size_t)row0 * D_MODEL + k0;
            astr = D_MODEL;
        } else {
            size_t base = (size_t)(k0 >> 6) * (N_TOK * HD) + (size_t)row0 * HD + (k0 & 63);
            Ah_g = g_C_hi + base;
            Al_g = g_C_lo + base;
            astr = HD;
        }
        uint32_t sb = sbase + (kc & 1) * G_STAGE;
#pragma unroll
        for (int i = 0; i < 2; i++) {
            int r = ld_r + 64 * i;
            uint32_t so = (uint32_t)(r * ASTR + ld_c) * 2;
            cp16(sb + so,              Ah_g + (size_t)r * astr + ld_c);
            cp16(sb + G_TILE + so,     Al_g + (size_t)r * astr + ld_c);
            cp16(sb + 2 * G_TILE + so, Bh_g + (size_t)r * D_MODEL + k0 + ld_c);
            cp16(sb + 3 * G_TILE + so, Bl_g + (size_t)r * D_MODEL + k0 + ld_c);
        }
        CP_COMMIT();
    };

    float acc[4][4][4] = {};

    issue_chunk(0);
    for (int kc = 0; kc < D_MODEL / KC; kc++) {
        CP_WAIT0();
        __syncthreads();
        if (kc + 1 < D_MODEL / KC) issue_chunk(kc + 1);

        const char* st = smc + (kc & 1) * G_STAGE;
        const __nv_bfloat16* sAh = (const __nv_bfloat16*)st;
        const __nv_bfloat16* sAl = (const __nv_bfloat16*)(st + G_TILE);
        const __nv_bfloat16* sBh = (const __nv_bfloat16*)(st + 2 * G_TILE);
        const __nv_bfloat16* sBl = (const __nv_bfloat16*)(st + 3 * G_TILE);

#pragma unroll
        for (int ks = 0; ks < KC; ks += 16) {
            uint32_t bh[4][2], bl[4][2];
#pragma unroll
            for (int nt = 0; nt < 4; nt++) {
                int n0 = wn * 32 + nt * 8 + g;
                bh[nt][0] = *(uint32_t*)&sBh[n0 * ASTR + ks + 2 * tig];
                bh[nt][1] = *(uint32_t*)&sBh[n0 * ASTR + ks + 8 + 2 * tig];
                bl[nt][0] = *(uint32_t*)&sBl[n0 * ASTR + ks + 2 * tig];
                bl[nt][1] = *(uint32_t*)&sBl[n0 * ASTR + ks + 8 + 2 * tig];
            }
#pragma unroll
            for (int mt = 0; mt < 4; mt++) {
                int r0 = wm * 64 + mt * 16 + g;
                uint32_t ah[4], al[4];
                ah[0] = *(uint32_t*)&sAh[r0 * ASTR + ks + 2 * tig];
                ah[1] = *(uint32_t*)&sAh[(r0 + 8) * ASTR + ks + 2 * tig];
                ah[2] = *(uint32_t*)&sAh[r0 * ASTR + ks + 8 + 2 * tig];
                ah[3] = *(uint32_t*)&sAh[(r0 + 8) * ASTR + ks + 8 + 2 * tig];
                al[0] = *(uint32_t*)&sAl[r0 * ASTR + ks + 2 * tig];
                al[1] = *(uint32_t*)&sAl[(r0 + 8) * ASTR + ks + 2 * tig];
                al[2] = *(uint32_t*)&sAl[r0 * ASTR + ks + 8 + 2 * tig];
                al[3] = *(uint32_t*)&sAl[(r0 + 8) * ASTR + ks + 8 + 2 * tig];
#pragma unroll
                for (int nt = 0; nt < 4; nt++) {
                    mma_bf16(acc[mt][nt], ah, bh[nt]);
                    mma_bf16(acc[mt][nt], ah, bl[nt]);
                    mma_bf16(acc[mt][nt], al, bh[nt]);
                }
            }
        }
        __syncthreads();
    }

    if (mode == 0) {
        const int head = (col0 + wn * 32) >> 6;
        // fold 1/sqrt(64) * log2(e) into Q (softmax runs in base-2 domain)
        const float sc = (which == 0) ? 0.125f * 1.4426950408889634f : 1.0f;
#pragma unroll
        for (int mt = 0; mt < 4; mt++) {
            int m = row0 + wm * 64 + mt * 16 + g;
#pragma unroll
            for (int nt = 0; nt < 4; nt++) {
                int eh = (wn * 32 + nt * 8 + 2 * tig) & 63;
                float v00 = acc[mt][nt][0] * sc, v01 = acc[mt][nt][1] * sc;
                float v10 = acc[mt][nt][2] * sc, v11 = acc[mt][nt][3] * sc;
                __nv_bfloat162 h0 = __floats2bfloat162_rn(v00, v01);
                __nv_bfloat162 h1 = __floats2bfloat162_rn(v10, v11);
                __nv_bfloat162 l0 = __floats2bfloat162_rn(v00 - __low2float(h0), v01 - __high2float(h0));
                __nv_bfloat162 l1 = __floats2bfloat162_rn(v10 - __low2float(h1), v11 - __high2float(h1));
                if (which == 2) {
                    size_t vb = (size_t)head * (HD * N_TOK);
                    g_Vth[vb + (size_t)eh * N_TOK + m]           = h0.x;
                    g_Vth[vb + (size_t)(eh + 1) * N_TOK + m]     = h0.y;
                    g_Vth[vb + (size_t)eh * N_TOK + m + 8]       = h1.x;
                    g_Vth[vb + (size_t)(eh + 1) * N_TOK + m + 8] = h1.y;
                    g_Vtl[vb + (size_t)eh * N_TOK + m]           = l0.x;
                    g_Vtl[vb + (size_t)(eh + 1) * N_TOK + m]     = l0.y;
                    g_Vtl[vb + (size_t)eh * N_TOK + m + 8]       = l1.x;
                    g_Vtl[vb + (size_t)(eh + 1) * N_TOK + m + 8] = l1.y;
                } else {
                    __nv_bfloat16* dh = (which == 0) ? g_Qh : g_Kh;
                    __nv_bfloat16* dl = (which == 0) ? g_Ql : g_Kl;
                    size_t b0 = (size_t)head * (N_TOK * HD) + (size_t)m * HD + eh;
                    size_t b1 = b0 + 8 * HD;
                    *(__nv_bfloat162*)(dh + b0) = h0;
                    *(__nv_bfloat162*)(dh + b1) = h1;
                    *(__nv_bfloat162*)(dl + b0) = l0;
                    *(__nv_bfloat162*)(dl + b1) = l1;
                }
            }
        }
    } else {
#pragma unroll
        for (int mt = 0; mt < 4; mt++) {
            int m = row0 + wm * 64 + mt * 16 + g;
#pragma unroll
            for (int nt = 0; nt < 4; nt++) {
                int e = col0 + wn * 32 + nt * 8 + 2 * tig;
                float2 b = *(const float2*)(bo + e);
                *(float2*)(out + (size_t)m * D_MODEL + e) =
                    make_float2(acc[mt][nt][0] + b.x, acc[mt][nt][1] + b.y);
                *(float2*)(out + (size_t)(m + 8) * D_MODEL + e) =
                    make_float2(acc[mt][nt][2] + b.x, acc[mt][nt][3] + b.y);
            }
        }
    }
}

// ---------------------------------------------------------------------------
// Tensor-core causal flash attention, cp.async double-buffered K/V tiles.
// CTA = 128 q x 128 k, 8 warps x 16 rows; softmax in registers (base-2).
// ---------------------------------------------------------------------------
#define AT_KSTR 72
#define AT_VSTR 136
#define AT_KBYTES (128 * AT_KSTR * 2)    // 18432
#define AT_VBYTES (64 * AT_VSTR * 2)     // 17408
#define AT_STAGE  (2 * AT_KBYTES + 2 * AT_VBYTES)  // 71680
#define AT_SMEM   (2 * AT_STAGE)                    // 143360

__global__ __launch_bounds__(256, 1) void attn_mma() {
    extern __shared__ char sma[];
    const uint32_t sbase = smem_u32(sma);

    const int h  = blockIdx.y;
    const int qt = (int)(gridDim.x - 1 - blockIdx.x);  // big tiles first
    const int q0 = qt * 128;
    const int t = threadIdx.x, wid = t >> 5, lane = t & 31;
    const int g = lane >> 2, tig = lane & 3;

    const __nv_bfloat16* Qh_g = g_Qh + (size_t)h * (N_TOK * HD);
    const __nv_bfloat16* Ql_g = g_Ql + (size_t)h * (N_TOK * HD);
    const __nv_bfloat16* Kh_g = g_Kh + (size_t)h * (N_TOK * HD);
    const __nv_bfloat16* Kl_g = g_Kl + (size_t)h * (N_TOK * HD);
    const __nv_bfloat16* Vh_g = g_Vth + (size_t)h * (HD * N_TOK);
    const __nv_bfloat16* Vl_g = g_Vtl + (size_t)h * (HD * N_TOK);

    auto issue_kv = [&](int kt) {
        const int k0 = kt * 128;
        uint32_t sb = sbase + (kt & 1) * AT_STAGE;
#pragma unroll
        for (int i = 0; i < 4; i++) {
            int idx = t + 256 * i;
            int r = idx >> 3, c8 = (idx & 7) * 8;
            uint32_t so = (uint32_t)(r * AT_KSTR + c8) * 2;
            cp16(sb + so,             Kh_g + (size_t)(k0 + r) * HD + c8);
            cp16(sb + AT_KBYTES + so, Kl_g + (size_t)(k0 + r) * HD + c8);
        }
#pragma unroll
        for (int i = 0; i < 4; i++) {
            int idx = t + 256 * i;
            int r = idx >> 4, c8 = (idx & 15) * 8;
            uint32_t so = (uint32_t)(r * AT_VSTR + c8) * 2;
            cp16(sb + 2 * AT_KBYTES + so,             Vh_g + (size_t)r * N_TOK + k0 + c8);
            cp16(sb + 2 * AT_KBYTES + AT_VBYTES + so, Vl_g + (size_t)r * N_TOK + k0 + c8);
        }
        CP_COMMIT();
    };

    issue_kv(0);

    const int qrow = q0 + wid * 16 + g;

    // Preload Q fragments (already scaled by log2e/8 at projection time)
    uint32_t qfh[4][4], qfl[4][4];
#pragma unroll
    for (int ks = 0; ks < 4; ks++) {
        int c = ks * 16 + 2 * tig;
        qfh[ks][0] = *(const uint32_t*)(Qh_g + (size_t)qrow * HD + c);
        qfh[ks][1] = *(const uint32_t*)(Qh_g + (size_t)(qrow + 8) * HD + c);
        qfh[ks][2] = *(const uint32_t*)(Qh_g + (size_t)qrow * HD + c + 8);
        qfh[ks][3] = *(const uint32_t*)(Qh_g + (size_t)(qrow + 8) * HD + c + 8);
        qfl[ks][0] = *(const uint32_t*)(Ql_g + (size_t)qrow * HD + c);
        qfl[ks][1] = *(const uint32_t*)(Ql_g + (size_t)(qrow + 8) * HD + c);
        qfl[ks][2] = *(const uint32_t*)(Ql_g + (size_t)qrow * HD + c + 8);
        qfl[ks][3] = *(const uint32_t*)(Ql_g + (size_t)(qrow + 8) * HD + c + 8);
    }

    const int rofs = (lane & 7) + ((lane & 16) >> 1);
    const int cofs = (lane & 8);
    const uint32_t kofs = (uint32_t)(rofs * AT_KSTR + cofs) * 2;
    const uint32_t vofs = (uint32_t)(rofs * AT_VSTR + cofs) * 2;

    float m0 = -1e30f, m1 = -1e30f, l0 = 0.0f, l1 = 0.0f;
    float o[8][4] = {};

    for (int kt = 0; kt <= qt; kt++) {
        CP_WAIT0();
        __syncthreads();
        if (kt + 1 <= qt) issue_kv(kt + 1);

        const uint32_t sb = sbase + (kt & 1) * AT_STAGE;
        const uint32_t kb_h = sb + kofs;
        const uint32_t kb_l = sb + AT_KBYTES + kofs;
        const uint32_t vb_h = sb + 2 * AT_KBYTES + vofs;
        const uint32_t vb_l = sb + 2 * AT_KBYTES + AT_VBYTES + vofs;
        const int k0 = kt * 128;

        // S = Q K^T
        float s[16][4];
#pragma unroll
        for (int nt = 0; nt < 16; nt++) { s[nt][0] = s[nt][1] = s[nt][2] = s[nt][3] = 0.0f; }
#pragma unroll
        for (int ks = 0; ks < 4; ks++) {
#pragma unroll
            for (int ntp = 0; ntp < 8; ntp++) {
                uint32_t bh[4], bl[4];
                uint32_t off = (uint32_t)(ntp * 16 * AT_KSTR + ks * 16) * 2;
                ldsm_x4(bh, kb_h + off);
                ldsm_x4(bl, kb_l + off);
                mma_bf16(s[2 * ntp],     qfh[ks], bh);
                mma_bf16(s[2 * ntp],     qfh[ks], bl);
                mma_bf16(s[2 * ntp],     qfl[ks], bh);
                mma_bf16(s[2 * ntp + 1], qfh[ks], bh + 2);
                mma_bf16(s[2 * ntp + 1], qfh[ks], bl + 2);
                mma_bf16(s[2 * ntp + 1], qfl[ks], bh + 2);
            }
        }

        if (kt == qt) {   // causal mask on diagonal tile
#pragma unroll
            for (int nt = 0; nt < 16; nt++) {
                int c = k0 + nt * 8 + 2 * tig;
                if (c     > qrow)     s[nt][0] = -1e30f;
                if (c + 1 > qrow)     s[nt][1] = -1e30f;
                if (c     > qrow + 8) s[nt][2] = -1e30f;
                if (c + 1 > qrow + 8) s[nt][3] = -1e30f;
            }
        }

        // Online softmax in base-2 (registers + shfl over 4 tig lanes)
        float mx0 = -1e30f, mx1 = -1e30f;
#pragma unroll
        for (int nt = 0; nt < 16; nt++) {
            mx0 = fmaxf(mx0, fmaxf(s[nt][0], s[nt][1]));
            mx1 = fmaxf(mx1, fmaxf(s[nt][2], s[nt][3]));
        }
        mx0 = fmaxf(mx0, __shfl_xor_sync(0xffffffffu, mx0, 1));
        mx0 = fmaxf(mx0, __shfl_xor_sync(0xffffffffu, mx0, 2));
        mx1 = fmaxf(mx1, __shfl_xor_sync(0xffffffffu, mx1, 1));
        mx1 = fmaxf(mx1, __shfl_xor_sync(0xffffffffu, mx1, 2));
        float mn0 = fmaxf(m0, mx0), mn1 = fmaxf(m1, mx1);
        float a0 = fast_exp2(m0 - mn0), a1 = fast_exp2(m1 - mn1);
        m0 = mn0; m1 = mn1;
        float sum0 = 0.0f, sum1 = 0.0f;
#pragma unroll
        for (int nt = 0; nt < 16; nt++) {
            s[nt][0] = fast_exp2(s[nt][0] - mn0);
            s[nt][1] = fast_exp2(s[nt][1] - mn0);
            s[nt][2] = fast_exp2(s[nt][2] - mn1);
            s[nt][3] = fast_exp2(s[nt][3] - mn1);
            sum0 += s[nt][0] + s[nt][1];
            sum1 += s[nt][2] + s[nt][3];
        }
        sum0 += __shfl_xor_sync(0xffffffffu, sum0, 1);
        sum0 += __shfl_xor_sync(0xffffffffu, sum0, 2);
        sum1 += __shfl_xor_sync(0xffffffffu, sum1, 1);
        sum1 += __shfl_xor_sync(0xffffffffu, sum1, 2);
        l0 = l0 * a0 + sum0;
        l1 = l1 * a1 + sum1;
#pragma unroll
        for (int f = 0; f < 8; f++) {
            o[f][0] *= a0; o[f][1] *= a0; o[f][2] *= a1; o[f][3] *= a1;
        }

        // O += P V  (P split hi/lo in registers; V via ldmatrix)
#pragma unroll
        for (int kk = 0; kk < 8; kk++) {
            uint32_t ph[4], pl[4];
            {
                __nv_bfloat162 t0 = __floats2bfloat162_rn(s[2 * kk][0], s[2 * kk][1]);
                __nv_bfloat162 t1 = __floats2bfloat162_rn(s[2 * kk][2], s[2 * kk][3]);
                __nv_bfloat162 t2 = __floats2bfloat162_rn(s[2 * kk + 1][0], s[2 * kk + 1][1]);
                __nv_bfloat162 t3 = __floats2bfloat162_rn(s[2 * kk + 1][2], s[2 * kk + 1][3]);
                ph[0] = *(uint32_t*)&t0; ph[1] = *(uint32_t*)&t1;
                ph[2] = *(uint32_t*)&t2; ph[3] = *(uint32_t*)&t3;
                __nv_bfloat162 u0 = __floats2bfloat162_rn(s[2 * kk][0] - __low2float(t0),
                                                          s[2 * kk][1] - __high2float(t0));
                __nv_bfloat162 u1 = __floats2bfloat162_rn(s[2 * kk][2] - __low2float(t1),
                                                          s[2 * kk][3] - __high2float(t1));
                __nv_bfloat162 u2 = __floats2bfloat162_rn(s[2 * kk + 1][0] - __low2float(t2),
                                                          s[2 * kk + 1][1] - __high2float(t2));
                __nv_bfloat162 u3 = __floats2bfloat162_rn(s[2 * kk + 1][2] - __low2float(t3),
                                                          s[2 * kk + 1][3] - __high2float(t3));
                pl[0] = *(uint32_t*)&u0; pl[1] = *(uint32_t*)&u1;
                pl[2] = *(uint32_t*)&u2; pl[3] = *(uint32_t*)&u3;
            }
#pragma unroll
            for (int dtp = 0; dtp < 4; dtp++) {
                uint32_t bh[4], bl[4];
                uint32_t off = (uint32_t)(dtp * 16 * AT_VSTR + kk * 16) * 2;
                ldsm_x4(bh, vb_h + off);
                ldsm_x4(bl, vb_l + off);
                mma_bf16(o[2 * dtp],     ph, bh);
                mma_bf16(o[2 * dtp],     ph, bl);
                mma_bf16(o[2 * dtp],     pl, bh);
                mma_bf16(o[2 * dtp + 1], ph, bh + 2);
                mma_bf16(o[2 * dtp + 1], ph, bl + 2);
                mma_bf16(o[2 * dtp + 1], pl, bh + 2);
            }
        }
        __syncthreads();
    }

    // Epilogue: normalize, split to bf16 hi/lo, write ctx head-major.
    float i0 = 1.0f / l0, i1 = 1.0f / l1;
#pragma unroll
    for (int f = 0; f < 8; f++) {
        int d = f * 8 + 2 * tig;
        float v00 = o[f][0] * i0, v01 = o[f][1] * i0;
        float v10 = o[f][2] * i1, v11 = o[f][3] * i1;
        __nv_bfloat162 h0 = __floats2bfloat162_rn(v00, v01);
        __nv_bfloat162 h1 = __floats2bfloat162_rn(v10, v11);
        __nv_bfloat162 e0 = __floats2bfloat162_rn(v00 - __low2float(h0), v01 - __high2float(h0));
        __nv_bfloat162 e1 = __floats2bfloat162_rn(v10 - __low2float(h1), v11 - __high2float(h1));
        size_t b0 = (size_t)h * (N_TOK * HD) + (size_t)qrow * HD + d;
        size_t b1 = b0 + 8 * HD;
        *(__nv_bfloat162*)(g_C_hi + b0) = h0;
        *(__nv_bfloat162*)(g_C_hi + b1) = h1;
        *(__nv_bfloat162*)(g_C_lo + b0) = e0;
        *(__nv_bfloat162*)(g_C_lo + b1) = e1;
    }
}

extern "C" void kernel_launch(void* const* d_in, const int* in_sizes, int n_in,
                              void* d_out, int out_size) {
    const float* x  = (const float*)d_in[0];
    const float* Wq = (const float*)d_in[1];
    const float* Wk = (const float*)d_in[2];
    const float* Wv = (const float*)d_in[3];
    const float* Wo = (const float*)d_in[4];
    const float* bo = (const float*)d_in[5];
    float* out = (float*)d_out;

    cudaFuncSetAttribute(attn_mma, cudaFuncAttributeMaxDynamicSharedMemorySize, AT_SMEM);
    cudaFuncSetAttribute(mma_gemm, cudaFuncAttributeMaxDynamicSharedMemorySize, G_SMEM);

    split_x<<<(N_TOK * D_MODEL / 4) / 256, 256>>>(x);
    wprep<<<dim3(32, 32, 4), dim3(32, 8)>>>(Wq, Wk, Wv, Wo);
    mma_gemm<<<dim3(8, 32, 3), 256, G_SMEM>>>(0, nullptr, nullptr);
    attn_mma<<<dim3(N_TOK / 128, NH), 256, AT_SMEM>>>();
    mma_gemm<<<dim3(8, 32, 1), 256, G_SMEM>>>(1, out, bo);
}

// round 8
// speedup vs baseline: 2.2981x; 1.1169x over previous
#include <cuda_runtime.h>
#include <cuda_bf16.h>
#include <cstdint>

#define N_TOK 4096
#define D_MODEL 1024
#define NH 16
#define HD 64

// ---------------------------------------------------------------------------
// Scratch (__device__ globals — no allocation).
// ---------------------------------------------------------------------------
__device__ __nv_bfloat16 g_x_hi[N_TOK * D_MODEL];
__device__ __nv_bfloat16 g_x_lo[N_TOK * D_MODEL];
__device__ __nv_bfloat16 g_WT_hi[4 * D_MODEL * D_MODEL];  // [which][e][k]
__device__ __nv_bfloat16 g_WT_lo[4 * D_MODEL * D_MODEL];
__device__ __nv_bfloat16 g_Qh[NH * N_TOK * HD];            // [h][tok][d], scaled log2e/8
__device__ __nv_bfloat16 g_Ql[NH * N_TOK * HD];
__device__ __nv_bfloat16 g_Kh[NH * N_TOK * HD];            // [h][tok][d]
__device__ __nv_bfloat16 g_Kl[NH * N_TOK * HD];
__device__ __nv_bfloat16 g_Vth[NH * HD * N_TOK];           // [h][d][tok] (transposed)
__device__ __nv_bfloat16 g_Vtl[NH * HD * N_TOK];
__device__ __nv_bfloat16 g_C_hi[NH * N_TOK * HD];          // ctx head-major
__device__ __nv_bfloat16 g_C_lo[NH * N_TOK * HD];

// HMMA m16n8k16 bf16 -> f32 accum (baseline PTX, works on sm_103 target)
__device__ __forceinline__ void mma_bf16(float* d, const uint32_t* a, const uint32_t* b) {
    asm volatile(
        "mma.sync.aligned.m16n8k16.row.col.f32.bf16.bf16.f32 "
        "{%0,%1,%2,%3}, {%4,%5,%6,%7}, {%8,%9}, {%0,%1,%2,%3};"
        : "+f"(d[0]), "+f"(d[1]), "+f"(d[2]), "+f"(d[3])
        : "r"(a[0]), "r"(a[1]), "r"(a[2]), "r"(a[3]), "r"(b[0]), "r"(b[1]));
}

__device__ __forceinline__ void ldsm_x4(uint32_t* r, uint32_t addr) {
    asm volatile("ldmatrix.sync.aligned.m8n8.x4.shared.b16 {%0,%1,%2,%3}, [%4];"
                 : "=r"(r[0]), "=r"(r[1]), "=r"(r[2]), "=r"(r[3]) : "r"(addr));
}

__device__ __forceinline__ uint32_t smem_u32(const void* p) {
    uint32_t a;
    asm("{ .reg .u64 t; cvta.to.shared.u64 t, %1; cvt.u32.u64 %0, t; }" : "=r"(a) : "l"(p));
    return a;
}

__device__ __forceinline__ void cp16(uint32_t saddr, const void* g) {
    asm volatile("cp.async.cg.shared.global [%0], [%1], 16;" :: "r"(saddr), "l"(g));
}
#define CP_COMMIT() asm volatile("cp.async.commit_group;" ::: "memory")
#define CP_WAIT0()  asm volatile("cp.async.wait_group 0;" ::: "memory")
#define CP_WAIT1()  asm volatile("cp.async.wait_group 1;" ::: "memory")

// Fast 2^y on the FMA pipe (no MUFU). rel err ~3e-6.
__device__ __forceinline__ float fast_exp2(float y) {
    y = fmaxf(y, -126.0f);
    float t = y + 12582912.0f;                       // 1.5 * 2^23
    int   i = __float_as_int(t) - 0x4B400000;
    float f = y - (t - 12582912.0f);                 // f in [-0.5, 0.5]
    float p =            1.3333558146e-3f;
    p = fmaf(p, f, 9.6181291057e-3f);
    p = fmaf(p, f, 5.5504108664e-2f);
    p = fmaf(p, f, 2.4022650696e-1f);
    p = fmaf(p, f, 6.9314718056e-1f);
    p = fmaf(p, f, 1.0f);
    return __int_as_float(__float_as_int(p) + (i << 23));
}

// ---------------------------------------------------------------------------
// Prep: split x into bf16 hi/lo (K-major, same layout as x).
// ---------------------------------------------------------------------------
__global__ __launch_bounds__(256) void split_x(const float* __restrict__ x) {
    int idx = blockIdx.x * 256 + threadIdx.x;
    float4 v = ((const float4*)x)[idx];
    __nv_bfloat162 h0 = __floats2bfloat162_rn(v.x, v.y);
    __nv_bfloat162 h1 = __floats2bfloat162_rn(v.z, v.w);
    float l0 = v.x - __low2float(h0), l1 = v.y - __high2float(h0);
    float l2 = v.z - __low2float(h1), l3 = v.w - __high2float(h1);
    ((__nv_bfloat162*)g_x_hi)[idx * 2]     = h0;
    ((__nv_bfloat162*)g_x_hi)[idx * 2 + 1] = h1;
    ((__nv_bfloat162*)g_x_lo)[idx * 2]     = __floats2bfloat162_rn(l0, l1);
    ((__nv_bfloat162*)g_x_lo)[idx * 2 + 1] = __floats2bfloat162_rn(l2, l3);
}

// ---------------------------------------------------------------------------
// Prep: WT[which][e][k] = W[k][e], split into bf16 hi/lo. 32x32 smem transpose.
// ---------------------------------------------------------------------------
__global__ void wprep(const float* __restrict__ Wq, const float* __restrict__ Wk,
                      const float* __restrict__ Wv, const float* __restrict__ Wo) {
    const int z = blockIdx.z;
    const float* W = (z == 0) ? Wq : (z == 1) ? Wk : (z == 2) ? Wv : Wo;
    __shared__ float ts[32][33];
    const int e0 = blockIdx.x * 32, k0 = blockIdx.y * 32;
    const int tx = threadIdx.x, ty = threadIdx.y;  // (32, 8)
#pragma unroll
    for (int i = 0; i < 4; i++)
        ts[ty + 8 * i][tx] = W[(size_t)(k0 + ty + 8 * i) * D_MODEL + e0 + tx];
    __syncthreads();
#pragma unroll
    for (int i = 0; i < 4; i++) {
        int row = ty + 8 * i;
        float v = ts[tx][row];
        __nv_bfloat16 hi = __float2bfloat16(v);
        float lo = v - __bfloat162float(hi);
        size_t o = (size_t)z * (D_MODEL * D_MODEL) + (size_t)(e0 + row) * D_MODEL + k0 + tx;
        g_WT_hi[o] = hi;
        g_WT_lo[o] = __float2bfloat16(lo);
    }
}

// ---------------------------------------------------------------------------
// HMMA bf16-split GEMM, cp.async double-buffered K chunks (one sync/iter).
// mode 0: qkv — epilogue splits hi/lo: Q (scaled log2e/8) & K row-major,
//         V transposed [h][d][tok].
// mode 1: oproj (A = ctx hi/lo head-major; out = d_out + bias, fp32)
// ---------------------------------------------------------------------------
#define KC 32
#define ASTR 40
#define G_TILE  (128 * ASTR * 2)        // 10240 B per tile
#define G_STAGE (4 * G_TILE)            // 40960 B per stage
#define G_SMEM  (2 * G_STAGE)           // 81920 B

__global__ __launch_bounds__(256, 2) void mma_gemm(int mode, float* __restrict__ out,
                                                   const float* __restrict__ bo) {
    extern __shared__ char smc[];
    const uint32_t sbase = smem_u32(smc);

    const int t = threadIdx.x;
    const int wid = t >> 5, lane = t & 31;
    const int wm = wid & 1, wn = wid >> 1;
    const int g = lane >> 2, tig = lane & 3;
    const int row0 = blockIdx.y * 128;
    const int col0 = blockIdx.x * 128;
    const int which = (mode == 0) ? blockIdx.z : 3;

    const __nv_bfloat16* Bh_g = g_WT_hi + (size_t)which * (D_MODEL * D_MODEL) + (size_t)col0 * D_MODEL;
    const __nv_bfloat16* Bl_g = g_WT_lo + (size_t)which * (D_MODEL * D_MODEL) + (size_t)col0 * D_MODEL;

    const int ld_r = t >> 2, ld_c = (t & 3) * 8;     // each thread: 2 rows x 8 bf16

    auto issue_chunk = [&](int kc) {
        const int k0 = kc * KC;
        const __nv_bfloat16 *Ah_g, *Al_g;
        int astr;
        if (mode == 0) {
            Ah_g = g_x_hi + (size_t)row0 * D_MODEL + k0;
            Al_g = g_x_lo + (size_t)row0 * D_MODEL + k0;
            astr = D_MODEL;
        } else {
            size_t base = (size_t)(k0 >> 6) * (N_TOK * HD) + (size_t)row0 * HD + (k0 & 63);
            Ah_g = g_C_hi + base;
            Al_g = g_C_lo + base;
            astr = HD;
        }
        uint32_t sb = sbase + (kc & 1) * G_STAGE;
#pragma unroll
        for (int i = 0; i < 2; i++) {
            int r = ld_r + 64 * i;
            uint32_t so = (uint32_t)(r * ASTR + ld_c) * 2;
            cp16(sb + so,              Ah_g + (size_t)r * astr + ld_c);
            cp16(sb + G_TILE + so,     Al_g + (size_t)r * astr + ld_c);
            cp16(sb + 2 * G_TILE + so, Bh_g + (size_t)r * D_MODEL + k0 + ld_c);
            cp16(sb + 3 * G_TILE + so, Bl_g + (size_t)r * D_MODEL + k0 + ld_c);
        }
        CP_COMMIT();
    };

    float acc[4][4][4] = {};

    issue_chunk(0);
    for (int kc = 0; kc < D_MODEL / KC; kc++) {
        CP_WAIT0();
        __syncthreads();   // single sync per iter: protects stage reuse + visibility
        if (kc + 1 < D_MODEL / KC) issue_chunk(kc + 1);

        const char* st = smc + (kc & 1) * G_STAGE;
        const __nv_bfloat16* sAh = (const __nv_bfloat16*)st;
        const __nv_bfloat16* sAl = (const __nv_bfloat16*)(st + G_TILE);
        const __nv_bfloat16* sBh = (const __nv_bfloat16*)(st + 2 * G_TILE);
        const __nv_bfloat16* sBl = (const __nv_bfloat16*)(st + 3 * G_TILE);

#pragma unroll
        for (int ks = 0; ks < KC; ks += 16) {
            uint32_t bh[4][2], bl[4][2];
#pragma unroll
            for (int nt = 0; nt < 4; nt++) {
                int n0 = wn * 32 + nt * 8 + g;
                bh[nt][0] = *(uint32_t*)&sBh[n0 * ASTR + ks + 2 * tig];
                bh[nt][1] = *(uint32_t*)&sBh[n0 * ASTR + ks + 8 + 2 * tig];
                bl[nt][0] = *(uint32_t*)&sBl[n0 * ASTR + ks + 2 * tig];
                bl[nt][1] = *(uint32_t*)&sBl[n0 * ASTR + ks + 8 + 2 * tig];
            }
#pragma unroll
            for (int mt = 0; mt < 4; mt++) {
                int r0 = wm * 64 + mt * 16 + g;
                uint32_t ah[4], al[4];
                ah[0] = *(uint32_t*)&sAh[r0 * ASTR + ks + 2 * tig];
                ah[1] = *(uint32_t*)&sAh[(r0 + 8) * ASTR + ks + 2 * tig];
                ah[2] = *(uint32_t*)&sAh[r0 * ASTR + ks + 8 + 2 * tig];
                ah[3] = *(uint32_t*)&sAh[(r0 + 8) * ASTR + ks + 8 + 2 * tig];
                al[0] = *(uint32_t*)&sAl[r0 * ASTR + ks + 2 * tig];
                al[1] = *(uint32_t*)&sAl[(r0 + 8) * ASTR + ks + 2 * tig];
                al[2] = *(uint32_t*)&sAl[r0 * ASTR + ks + 8 + 2 * tig];
                al[3] = *(uint32_t*)&sAl[(r0 + 8) * ASTR + ks + 8 + 2 * tig];
#pragma unroll
                for (int nt = 0; nt < 4; nt++) {
                    mma_bf16(acc[mt][nt], ah, bh[nt]);
                    mma_bf16(acc[mt][nt], ah, bl[nt]);
                    mma_bf16(acc[mt][nt], al, bh[nt]);
                }
            }
        }
    }

    if (mode == 0) {
        const int head = (col0 + wn * 32) >> 6;
        // fold 1/sqrt(64) * log2(e) into Q (softmax runs in base-2 domain)
        const float sc = (which == 0) ? 0.125f * 1.4426950408889634f : 1.0f;
#pragma unroll
        for (int mt = 0; mt < 4; mt++) {
            int m = row0 + wm * 64 + mt * 16 + g;
#pragma unroll
            for (int nt = 0; nt < 4; nt++) {
                int eh = (wn * 32 + nt * 8 + 2 * tig) & 63;
                float v00 = acc[mt][nt][0] * sc, v01 = acc[mt][nt][1] * sc;
                float v10 = acc[mt][nt][2] * sc, v11 = acc[mt][nt][3] * sc;
                __nv_bfloat162 h0 = __floats2bfloat162_rn(v00, v01);
                __nv_bfloat162 h1 = __floats2bfloat162_rn(v10, v11);
                __nv_bfloat162 l0 = __floats2bfloat162_rn(v00 - __low2float(h0), v01 - __high2float(h0));
                __nv_bfloat162 l1 = __floats2bfloat162_rn(v10 - __low2float(h1), v11 - __high2float(h1));
                if (which == 2) {
                    size_t vb = (size_t)head * (HD * N_TOK);
                    g_Vth[vb + (size_t)eh * N_TOK + m]           = h0.x;
                    g_Vth[vb + (size_t)(eh + 1) * N_TOK + m]     = h0.y;
                    g_Vth[vb + (size_t)eh * N_TOK + m + 8]       = h1.x;
                    g_Vth[vb + (size_t)(eh + 1) * N_TOK + m + 8] = h1.y;
                    g_Vtl[vb + (size_t)eh * N_TOK + m]           = l0.x;
                    g_Vtl[vb + (size_t)(eh + 1) * N_TOK + m]     = l0.y;
                    g_Vtl[vb + (size_t)eh * N_TOK + m + 8]       = l1.x;
                    g_Vtl[vb + (size_t)(eh + 1) * N_TOK + m + 8] = l1.y;
                } else {
                    __nv_bfloat16* dh = (which == 0) ? g_Qh : g_Kh;
                    __nv_bfloat16* dl = (which == 0) ? g_Ql : g_Kl;
                    size_t b0 = (size_t)head * (N_TOK * HD) + (size_t)m * HD + eh;
                    size_t b1 = b0 + 8 * HD;
                    *(__nv_bfloat162*)(dh + b0) = h0;
                    *(__nv_bfloat162*)(dh + b1) = h1;
                    *(__nv_bfloat162*)(dl + b0) = l0;
                    *(__nv_bfloat162*)(dl + b1) = l1;
                }
            }
        }
    } else {
#pragma unroll
        for (int mt = 0; mt < 4; mt++) {
            int m = row0 + wm * 64 + mt * 16 + g;
#pragma unroll
            for (int nt = 0; nt < 4; nt++) {
                int e = col0 + wn * 32 + nt * 8 + 2 * tig;
                float2 b = *(const float2*)(bo + e);
                *(float2*)(out + (size_t)m * D_MODEL + e) =
                    make_float2(acc[mt][nt][0] + b.x, acc[mt][nt][1] + b.y);
                *(float2*)(out + (size_t)(m + 8) * D_MODEL + e) =
                    make_float2(acc[mt][nt][2] + b.x, acc[mt][nt][3] + b.y);
            }
        }
    }
}

// ---------------------------------------------------------------------------
// Tensor-core causal flash attention, 3-stage cp.async pipeline, ONE sync/iter.
// CTA = 128 q x 128 k, 8 warps x 16 rows; softmax in registers (base-2).
// grid = (NH, 32 tiles), qt = 31 - blockIdx.y  => global longest-first order.
// ---------------------------------------------------------------------------
#define AT_KSTR 72
#define AT_VSTR 136
#define AT_KBYTES (128 * AT_KSTR * 2)    // 18432
#define AT_VBYTES (64 * AT_VSTR * 2)     // 17408
#define AT_STAGE  (2 * AT_KBYTES + 2 * AT_VBYTES)  // 71680
#define AT_SMEM   (3 * AT_STAGE)                    // 215040

__global__ __launch_bounds__(256, 1) void attn_mma() {
    extern __shared__ char sma[];
    const uint32_t sbase = smem_u32(sma);

    const int h  = blockIdx.x;
    const int qt = (int)(gridDim.y - 1 - blockIdx.y);  // global longest-first
    const int q0 = qt * 128;
    const int t = threadIdx.x, wid = t >> 5, lane = t & 31;
    const int g = lane >> 2, tig = lane & 3;

    const __nv_bfloat16* Qh_g = g_Qh + (size_t)h * (N_TOK * HD);
    const __nv_bfloat16* Ql_g = g_Ql + (size_t)h * (N_TOK * HD);
    const __nv_bfloat16* Kh_g = g_Kh + (size_t)h * (N_TOK * HD);
    const __nv_bfloat16* Kl_g = g_Kl + (size_t)h * (N_TOK * HD);
    const __nv_bfloat16* Vh_g = g_Vth + (size_t)h * (HD * N_TOK);
    const __nv_bfloat16* Vl_g = g_Vtl + (size_t)h * (HD * N_TOK);

    auto issue_kv = [&](int kt, int stage) {
        const int k0 = kt * 128;
        uint32_t sb = sbase + stage * AT_STAGE;
#pragma unroll
        for (int i = 0; i < 4; i++) {
            int idx = t + 256 * i;
            int r = idx >> 3, c8 = (idx & 7) * 8;
            uint32_t so = (uint32_t)(r * AT_KSTR + c8) * 2;
            cp16(sb + so,             Kh_g + (size_t)(k0 + r) * HD + c8);
            cp16(sb + AT_KBYTES + so, Kl_g + (size_t)(k0 + r) * HD + c8);
        }
#pragma unroll
        for (int i = 0; i < 4; i++) {
            int idx = t + 256 * i;
            int r = idx >> 4, c8 = (idx & 15) * 8;
            uint32_t so = (uint32_t)(r * AT_VSTR + c8) * 2;
            cp16(sb + 2 * AT_KBYTES + so,             Vh_g + (size_t)r * N_TOK + k0 + c8);
            cp16(sb + 2 * AT_KBYTES + AT_VBYTES + so, Vl_g + (size_t)r * N_TOK + k0 + c8);
        }
        CP_COMMIT();
    };

    // Prologue: keep exactly 2 groups in flight (duplicates beyond qt are
    // written to stages that are never read).
    issue_kv(0, 0);
    issue_kv(qt >= 1 ? 1 : 0, 1);

    const int qrow = q0 + wid * 16 + g;

    // Preload Q fragments (already scaled by log2e/8 at projection time)
    uint32_t qfh[4][4], qfl[4][4];
#pragma unroll
    for (int ks = 0; ks < 4; ks++) {
        int c = ks * 16 + 2 * tig;
        qfh[ks][0] = *(const uint32_t*)(Qh_g + (size_t)qrow * HD + c);
        qfh[ks][1] = *(const uint32_t*)(Qh_g + (size_t)(qrow + 8) * HD + c);
        qfh[ks][2] = *(const uint32_t*)(Qh_g + (size_t)qrow * HD + c + 8);
        qfh[ks][3] = *(const uint32_t*)(Qh_g + (size_t)(qrow + 8) * HD + c + 8);
        qfl[ks][0] = *(const uint32_t*)(Ql_g + (size_t)qrow * HD + c);
        qfl[ks][1] = *(const uint32_t*)(Ql_g + (size_t)(qrow + 8) * HD + c);
        qfl[ks][2] = *(const uint32_t*)(Ql_g + (size_t)qrow * HD + c + 8);
        qfl[ks][3] = *(const uint32_t*)(Ql_g + (size_t)(qrow + 8) * HD + c + 8);
    }

    const int rofs = (lane & 7) + ((lane & 16) >> 1);
    const int cofs = (lane & 8);
    const uint32_t kofs = (uint32_t)(rofs * AT_KSTR + cofs) * 2;
    const uint32_t vofs = (uint32_t)(rofs * AT_VSTR + cofs) * 2;

    float m0 = -1e30f, m1 = -1e30f, l0 = 0.0f, l1 = 0.0f;
    float o[8][4] = {};

    int stage = 0;
    for (int kt = 0; kt <= qt; kt++) {
        CP_WAIT1();          // stage `stage` (tile kt) is complete
        __syncthreads();     // all warps done with the stage being overwritten next
        {
            int nxt = kt + 2;
            issue_kv(nxt <= qt ? nxt : qt, (stage + 2) % 3);
        }

        const uint32_t sb = sbase + stage * AT_STAGE;
        const uint32_t kb_h = sb + kofs;
        const uint32_t kb_l = sb + AT_KBYTES + kofs;
        const uint32_t vb_h = sb + 2 * AT_KBYTES + vofs;
        const uint32_t vb_l = sb + 2 * AT_KBYTES + AT_VBYTES + vofs;
        const int k0 = kt * 128;
        stage = (stage + 1) % 3;

        // S = Q K^T
        float s[16][4];
#pragma unroll
        for (int nt = 0; nt < 16; nt++) { s[nt][0] = s[nt][1] = s[nt][2] = s[nt][3] = 0.0f; }
#pragma unroll
        for (int ks = 0; ks < 4; ks++) {
#pragma unroll
            for (int ntp = 0; ntp < 8; ntp++) {
                uint32_t bh[4], bl[4];
                uint32_t off = (uint32_t)(ntp * 16 * AT_KSTR + ks * 16) * 2;
                ldsm_x4(bh, kb_h + off);
                ldsm_x4(bl, kb_l + off);
                mma_bf16(s[2 * ntp],     qfh[ks], bh);
                mma_bf16(s[2 * ntp],     qfh[ks], bl);
                mma_bf16(s[2 * ntp],     qfl[ks], bh);
                mma_bf16(s[2 * ntp + 1], qfh[ks], bh + 2);
                mma_bf16(s[2 * ntp + 1], qfh[ks], bl + 2);
                mma_bf16(s[2 * ntp + 1], qfl[ks], bh + 2);
            }
        }

        if (kt == qt) {   // causal mask on diagonal tile
#pragma unroll
            for (int nt = 0; nt < 16; nt++) {
                int c = k0 + nt * 8 + 2 * tig;
                if (c     > qrow)     s[nt][0] = -1e30f;
                if (c + 1 > qrow)     s[nt][1] = -1e30f;
                if (c     > qrow + 8) s[nt][2] = -1e30f;
                if (c + 1 > qrow + 8) s[nt][3] = -1e30f;
            }
        }

        // Online softmax in base-2 (registers + shfl over 4 tig lanes)
        float mx0 = -1e30f, mx1 = -1e30f;
#pragma unroll
        for (int nt = 0; nt < 16; nt++) {
            mx0 = fmaxf(mx0, fmaxf(s[nt][0], s[nt][1]));
            mx1 = fmaxf(mx1, fmaxf(s[nt][2], s[nt][3]));
        }
        mx0 = fmaxf(mx0, __shfl_xor_sync(0xffffffffu, mx0, 1));
        mx0 = fmaxf(mx0, __shfl_xor_sync(0xffffffffu, mx0, 2));
        mx1 = fmaxf(mx1, __shfl_xor_sync(0xffffffffu, mx1, 1));
        mx1 = fmaxf(mx1, __shfl_xor_sync(0xffffffffu, mx1, 2));
        float mn0 = fmaxf(m0, mx0), mn1 = fmaxf(m1, mx1);
        float a0 = fast_exp2(m0 - mn0), a1 = fast_exp2(m1 - mn1);
        m0 = mn0; m1 = mn1;
        float sum0 = 0.0f, sum1 = 0.0f;
#pragma unroll
        for (int nt = 0; nt < 16; nt++) {
            s[nt][0] = fast_exp2(s[nt][0] - mn0);
            s[nt][1] = fast_exp2(s[nt][1] - mn0);
            s[nt][2] = fast_exp2(s[nt][2] - mn1);
            s[nt][3] = fast_exp2(s[nt][3] - mn1);
            sum0 += s[nt][0] + s[nt][1];
            sum1 += s[nt][2] + s[nt][3];
        }
        sum0 += __shfl_xor_sync(0xffffffffu, sum0, 1);
        sum0 += __shfl_xor_sync(0xffffffffu, sum0, 2);
        sum1 += __shfl_xor_sync(0xffffffffu, sum1, 1);
        sum1 += __shfl_xor_sync(0xffffffffu, sum1, 2);
        l0 = l0 * a0 + sum0;
        l1 = l1 * a1 + sum1;
#pragma unroll
        for (int f = 0; f < 8; f++) {
            o[f][0] *= a0; o[f][1] *= a0; o[f][2] *= a1; o[f][3] *= a1;
        }

        // O += P V  (P split hi/lo in registers; V via ldmatrix)
#pragma unroll
        for (int kk = 0; kk < 8; kk++) {
            uint32_t ph[4], pl[4];
            {
                __nv_bfloat162 t0 = __floats2bfloat162_rn(s[2 * kk][0], s[2 * kk][1]);
                __nv_bfloat162 t1 = __floats2bfloat162_rn(s[2 * kk][2], s[2 * kk][3]);
                __nv_bfloat162 t2 = __floats2bfloat162_rn(s[2 * kk + 1][0], s[2 * kk + 1][1]);
                __nv_bfloat162 t3 = __floats2bfloat162_rn(s[2 * kk + 1][2], s[2 * kk + 1][3]);
                ph[0] = *(uint32_t*)&t0; ph[1] = *(uint32_t*)&t1;
                ph[2] = *(uint32_t*)&t2; ph[3] = *(uint32_t*)&t3;
                __nv_bfloat162 u0 = __floats2bfloat162_rn(s[2 * kk][0] - __low2float(t0),
                                                          s[2 * kk][1] - __high2float(t0));
                __nv_bfloat162 u1 = __floats2bfloat162_rn(s[2 * kk][2] - __low2float(t1),
                                                          s[2 * kk][3] - __high2float(t1));
                __nv_bfloat162 u2 = __floats2bfloat162_rn(s[2 * kk + 1][0] - __low2float(t2),
                                                          s[2 * kk + 1][1] - __high2float(t2));
                __nv_bfloat162 u3 = __floats2bfloat162_rn(s[2 * kk + 1][2] - __low2float(t3),
                                                          s[2 * kk + 1][3] - __high2float(t3));
                pl[0] = *(uint32_t*)&u0; pl[1] = *(uint32_t*)&u1;
                pl[2] = *(uint32_t*)&u2; pl[3] = *(uint32_t*)&u3;
            }
#pragma unroll
            for (int dtp = 0; dtp < 4; dtp++) {
                uint32_t bh[4], bl[4];
                uint32_t off = (uint32_t)(dtp * 16 * AT_VSTR + kk * 16) * 2;
                ldsm_x4(bh, vb_h + off);
                ldsm_x4(bl, vb_l + off);
                mma_bf16(o[2 * dtp],     ph, bh);
                mma_bf16(o[2 * dtp],     ph, bl);
                mma_bf16(o[2 * dtp],     pl, bh);
                mma_bf16(o[2 * dtp + 1], ph, bh + 2);
                mma_bf16(o[2 * dtp + 1], ph, bl + 2);
                mma_bf16(o[2 * dtp + 1], pl, bh + 2);
            }
        }
    }
    CP_WAIT0();   // drain outstanding prefetches before exit

    // Epilogue: normalize, split to bf16 hi/lo, write ctx head-major.
    float i0 = 1.0f / l0, i1 = 1.0f / l1;
#pragma unroll
    for (int f = 0; f < 8; f++) {
        int d = f * 8 + 2 * tig;
        float v00 = o[f][0] * i0, v01 = o[f][1] * i0;
        float v10 = o[f][2] * i1, v11 = o[f][3] * i1;
        __nv_bfloat162 h0 = __floats2bfloat162_rn(v00, v01);
        __nv_bfloat162 h1 = __floats2bfloat162_rn(v10, v11);
        __nv_bfloat162 e0 = __floats2bfloat162_rn(v00 - __low2float(h0), v01 - __high2float(h0));
        __nv_bfloat162 e1 = __floats2bfloat162_rn(v10 - __low2float(h1), v11 - __high2float(h1));
        size_t b0 = (size_t)h * (N_TOK * HD) + (size_t)qrow * HD + d;
        size_t b1 = b0 + 8 * HD;
        *(__nv_bfloat162*)(g_C_hi + b0) = h0;
        *(__nv_bfloat162*)(g_C_hi + b1) = h1;
        *(__nv_bfloat162*)(g_C_lo + b0) = e0;
        *(__nv_bfloat162*)(g_C_lo + b1) = e1;
    }
}

extern "C" void kernel_launch(void* const* d_in, const int* in_sizes, int n_in,
                              void* d_out, int out_size) {
    const float* x  = (const float*)d_in[0];
    const float* Wq = (const float*)d_in[1];
    const float* Wk = (const float*)d_in[2];
    const float* Wv = (const float*)d_in[3];
    const float* Wo = (const float*)d_in[4];
    const float* bo = (const float*)d_in[5];
    float* out = (float*)d_out;

    cudaFuncSetAttribute(attn_mma, cudaFuncAttributeMaxDynamicSharedMemorySize, AT_SMEM);
    cudaFuncSetAttribute(mma_gemm, cudaFuncAttributeMaxDynamicSharedMemorySize, G_SMEM);

    split_x<<<(N_TOK * D_MODEL / 4) / 256, 256>>>(x);
    wprep<<<dim3(32, 32, 4), dim3(32, 8)>>>(Wq, Wk, Wv, Wo);
    mma_gemm<<<dim3(8, 32, 3), 256, G_SMEM>>>(0, nullptr, nullptr);
    attn_mma<<<dim3(NH, N_TOK / 128), 256, AT_SMEM>>>();
    mma_gemm<<<dim3(8, 32, 1), 256, G_SMEM>>>(1, out, bo);
}

// round 9
// speedup vs baseline: 2.4030x; 1.0457x over previous
#include <cuda_runtime.h>
#include <cuda_bf16.h>
#include <cstdint>

#define N_TOK 4096
#define D_MODEL 1024
#define NH 16
#define HD 64

// ---------------------------------------------------------------------------
// Scratch (__device__ globals — no allocation).
// ---------------------------------------------------------------------------
__device__ __nv_bfloat16 g_x_hi[N_TOK * D_MODEL];
__device__ __nv_bfloat16 g_x_lo[N_TOK * D_MODEL];
__device__ __nv_bfloat16 g_WT_hi[4 * D_MODEL * D_MODEL];  // [which][e][k]
__device__ __nv_bfloat16 g_WT_lo[4 * D_MODEL * D_MODEL];
__device__ __nv_bfloat16 g_Qh[NH * N_TOK * HD];            // [h][tok][d], scaled log2e/8
__device__ __nv_bfloat16 g_Ql[NH * N_TOK * HD];
__device__ __nv_bfloat16 g_Kh[NH * N_TOK * HD];            // [h][tok][d]
__device__ __nv_bfloat16 g_Kl[NH * N_TOK * HD];
__device__ __nv_bfloat16 g_Vth[NH * HD * N_TOK];           // [h][d][tok] (transposed)
__device__ __nv_bfloat16 g_Vtl[NH * HD * N_TOK];
__device__ __nv_bfloat16 g_C_hi[NH * N_TOK * HD];          // ctx head-major
__device__ __nv_bfloat16 g_C_lo[NH * N_TOK * HD];

// HMMA m16n8k16 bf16 -> f32 accum (baseline PTX, works on sm_103 target)
__device__ __forceinline__ void mma_bf16(float* d, const uint32_t* a, const uint32_t* b) {
    asm volatile(
        "mma.sync.aligned.m16n8k16.row.col.f32.bf16.bf16.f32 "
        "{%0,%1,%2,%3}, {%4,%5,%6,%7}, {%8,%9}, {%0,%1,%2,%3};"
        : "+f"(d[0]), "+f"(d[1]), "+f"(d[2]), "+f"(d[3])
        : "r"(a[0]), "r"(a[1]), "r"(a[2]), "r"(a[3]), "r"(b[0]), "r"(b[1]));
}

__device__ __forceinline__ void ldsm_x4(uint32_t* r, uint32_t addr) {
    asm volatile("ldmatrix.sync.aligned.m8n8.x4.shared.b16 {%0,%1,%2,%3}, [%4];"
                 : "=r"(r[0]), "=r"(r[1]), "=r"(r[2]), "=r"(r[3]) : "r"(addr));
}

__device__ __forceinline__ uint32_t smem_u32(const void* p) {
    uint32_t a;
    asm("{ .reg .u64 t; cvta.to.shared.u64 t, %1; cvt.u32.u64 %0, t; }" : "=r"(a) : "l"(p));
    return a;
}

__device__ __forceinline__ void cp16(uint32_t saddr, const void* g) {
    asm volatile("cp.async.cg.shared.global [%0], [%1], 16;" :: "r"(saddr), "l"(g));
}
#define CP_COMMIT() asm volatile("cp.async.commit_group;" ::: "memory")
#define CP_WAIT0()  asm volatile("cp.async.wait_group 0;" ::: "memory")
#define CP_WAIT1()  asm volatile("cp.async.wait_group 1;" ::: "memory")

// Fast 2^y on the FMA pipe (no MUFU). rel err ~3e-6.
__device__ __forceinline__ float fast_exp2(float y) {
    y = fmaxf(y, -126.0f);
    float t = y + 12582912.0f;                       // 1.5 * 2^23
    int   i = __float_as_int(t) - 0x4B400000;
    float f = y - (t - 12582912.0f);                 // f in [-0.5, 0.5]
    float p =            1.3333558146e-3f;
    p = fmaf(p, f, 9.6181291057e-3f);
    p = fmaf(p, f, 5.5504108664e-2f);
    p = fmaf(p, f, 2.4022650696e-1f);
    p = fmaf(p, f, 6.9314718056e-1f);
    p = fmaf(p, f, 1.0f);
    return __int_as_float(__float_as_int(p) + (i << 23));
}

// ---------------------------------------------------------------------------
// Prep: split x into bf16 hi/lo (K-major, same layout as x).
// ---------------------------------------------------------------------------
__global__ __launch_bounds__(256) void split_x(const float* __restrict__ x) {
    int idx = blockIdx.x * 256 + threadIdx.x;
    float4 v = ((const float4*)x)[idx];
    __nv_bfloat162 h0 = __floats2bfloat162_rn(v.x, v.y);
    __nv_bfloat162 h1 = __floats2bfloat162_rn(v.z, v.w);
    float l0 = v.x - __low2float(h0), l1 = v.y - __high2float(h0);
    float l2 = v.z - __low2float(h1), l3 = v.w - __high2float(h1);
    ((__nv_bfloat162*)g_x_hi)[idx * 2]     = h0;
    ((__nv_bfloat162*)g_x_hi)[idx * 2 + 1] = h1;
    ((__nv_bfloat162*)g_x_lo)[idx * 2]     = __floats2bfloat162_rn(l0, l1);
    ((__nv_bfloat162*)g_x_lo)[idx * 2 + 1] = __floats2bfloat162_rn(l2, l3);
}

// ---------------------------------------------------------------------------
// Prep: WT[which][e][k] = W[k][e], split into bf16 hi/lo. 32x32 smem transpose.
// ---------------------------------------------------------------------------
__global__ void wprep(const float* __restrict__ Wq, const float* __restrict__ Wk,
                      const float* __restrict__ Wv, const float* __restrict__ Wo) {
    const int z = blockIdx.z;
    const float* W = (z == 0) ? Wq : (z == 1) ? Wk : (z == 2) ? Wv : Wo;
    __shared__ float ts[32][33];
    const int e0 = blockIdx.x * 32, k0 = blockIdx.y * 32;
    const int tx = threadIdx.x, ty = threadIdx.y;  // (32, 8)
#pragma unroll
    for (int i = 0; i < 4; i++)
        ts[ty + 8 * i][tx] = W[(size_t)(k0 + ty + 8 * i) * D_MODEL + e0 + tx];
    __syncthreads();
#pragma unroll
    for (int i = 0; i < 4; i++) {
        int row = ty + 8 * i;
        float v = ts[tx][row];
        __nv_bfloat16 hi = __float2bfloat16(v);
        float lo = v - __bfloat162float(hi);
        size_t o = (size_t)z * (D_MODEL * D_MODEL) + (size_t)(e0 + row) * D_MODEL + k0 + tx;
        g_WT_hi[o] = hi;
        g_WT_lo[o] = __float2bfloat16(lo);
    }
}

// ---------------------------------------------------------------------------
// HMMA bf16-split GEMM, cp.async double-buffered, ldmatrix fragment loads.
// mode 0: qkv — epilogue splits hi/lo: Q (scaled log2e/8) & K row-major,
//         V transposed [h][d][tok].
// mode 1: oproj (A = ctx hi/lo head-major; out = d_out + bias, fp32)
// ---------------------------------------------------------------------------
#define KC 32
#define ASTR 40
#define G_TILE  (128 * ASTR * 2)        // 10240 B per tile
#define G_STAGE (4 * G_TILE)            // 40960 B per stage
#define G_SMEM  (2 * G_STAGE)           // 81920 B

__global__ __launch_bounds__(256, 2) void mma_gemm(int mode, float* __restrict__ out,
                                                   const float* __restrict__ bo) {
    extern __shared__ char smc[];
    const uint32_t sbase = smem_u32(smc);

    const int t = threadIdx.x;
    const int wid = t >> 5, lane = t & 31;
    const int wm = wid & 1, wn = wid >> 1;
    const int g = lane >> 2, tig = lane & 3;
    const int row0 = blockIdx.y * 128;
    const int col0 = blockIdx.x * 128;
    const int which = (mode == 0) ? blockIdx.z : 3;

    const __nv_bfloat16* Bh_g = g_WT_hi + (size_t)which * (D_MODEL * D_MODEL) + (size_t)col0 * D_MODEL;
    const __nv_bfloat16* Bl_g = g_WT_lo + (size_t)which * (D_MODEL * D_MODEL) + (size_t)col0 * D_MODEL;

    const int ld_r = t >> 2, ld_c = (t & 3) * 8;     // each thread: 2 rows x 8 bf16

    auto issue_chunk = [&](int kc) {
        const int k0 = kc * KC;
        const __nv_bfloat16 *Ah_g, *Al_g;
        int astr;
        if (mode == 0) {
            Ah_g = g_x_hi + (size_t)row0 * D_MODEL + k0;
            Al_g = g_x_lo + (size_t)row0 * D_MODEL + k0;
            astr = D_MODEL;
        } else {
            size_t base = (size_t)(k0 >> 6) * (N_TOK * HD) + (size_t)row0 * HD + (k0 & 63);
            Ah_g = g_C_hi + base;
            Al_g = g_C_lo + base;
            astr = HD;
        }
        uint32_t sb = sbase + (kc & 1) * G_STAGE;
#pragma unroll
        for (int i = 0; i < 2; i++) {
            int r = ld_r + 64 * i;
            uint32_t so = (uint32_t)(r * ASTR + ld_c) * 2;
            cp16(sb + so,              Ah_g + (size_t)r * astr + ld_c);
            cp16(sb + G_TILE + so,     Al_g + (size_t)r * astr + ld_c);
            cp16(sb + 2 * G_TILE + so, Bh_g + (size_t)r * D_MODEL + k0 + ld_c);
            cp16(sb + 3 * G_TILE + so, Bl_g + (size_t)r * D_MODEL + k0 + ld_c);
        }
        CP_COMMIT();
    };

    // ldmatrix lane offsets.
    // A tiles (order a0,a1,a2,a3 = r0c0, r8c0, r0c8, r8c8):
    const int arofs = (lane & 7) + (lane & 8);            // +8 rows for lanes 8-15, 24-31
    const int acofs = (lane & 16) >> 1;                   // +8 cols for lanes 16+
    // B tiles (order b0(nt0), b1(nt0), b0(nt1), b1(nt1) = r0c0, r0c8, r8c0, r8c8):
    const int brofs = (lane & 7) + ((lane & 16) >> 1);
    const int bcofs = (lane & 8);

    float acc[4][4][4] = {};

    issue_chunk(0);
    for (int kc = 0; kc < D_MODEL / KC; kc++) {
        CP_WAIT0();
        __syncthreads();   // single sync per iter: protects stage reuse + visibility
        if (kc + 1 < D_MODEL / KC) issue_chunk(kc + 1);

        const uint32_t st = sbase + (kc & 1) * G_STAGE;
        const uint32_t sAh = st;
        const uint32_t sAl = st + G_TILE;
        const uint32_t sBh = st + 2 * G_TILE;
        const uint32_t sBl = st + 3 * G_TILE;

#pragma unroll
        for (int ks = 0; ks < KC; ks += 16) {
            // B fragments: 2 ldmatrix.x4 per precision (each covers 2 n-tiles)
            uint32_t bh[4][2], bl[4][2];
#pragma unroll
            for (int p = 0; p < 2; p++) {
                uint32_t off = (uint32_t)((wn * 32 + p * 16 + brofs) * ASTR + ks + bcofs) * 2;
                uint32_t rb[4];
                ldsm_x4(rb, sBh + off);
                bh[2 * p][0] = rb[0]; bh[2 * p][1] = rb[1];
                bh[2 * p + 1][0] = rb[2]; bh[2 * p + 1][1] = rb[3];
                ldsm_x4(rb, sBl + off);
                bl[2 * p][0] = rb[0]; bl[2 * p][1] = rb[1];
                bl[2 * p + 1][0] = rb[2]; bl[2 * p + 1][1] = rb[3];
            }
#pragma unroll
            for (int mt = 0; mt < 4; mt++) {
                uint32_t off = (uint32_t)((wm * 64 + mt * 16 + arofs) * ASTR + ks + acofs) * 2;
                uint32_t ah[4], al[4];
                ldsm_x4(ah, sAh + off);
                ldsm_x4(al, sAl + off);
#pragma unroll
                for (int nt = 0; nt < 4; nt++) {
                    mma_bf16(acc[mt][nt], ah, bh[nt]);
                    mma_bf16(acc[mt][nt], ah, bl[nt]);
                    mma_bf16(acc[mt][nt], al, bh[nt]);
                }
            }
        }
    }

    if (mode == 0) {
        const int head = (col0 + wn * 32) >> 6;
        // fold 1/sqrt(64) * log2(e) into Q (softmax runs in base-2 domain)
        const float sc = (which == 0) ? 0.125f * 1.4426950408889634f : 1.0f;
#pragma unroll
        for (int mt = 0; mt < 4; mt++) {
            int m = row0 + wm * 64 + mt * 16 + g;
#pragma unroll
            for (int nt = 0; nt < 4; nt++) {
                int eh = (wn * 32 + nt * 8 + 2 * tig) & 63;
                float v00 = acc[mt][nt][0] * sc, v01 = acc[mt][nt][1] * sc;
                float v10 = acc[mt][nt][2] * sc, v11 = acc[mt][nt][3] * sc;
                __nv_bfloat162 h0 = __floats2bfloat162_rn(v00, v01);
                __nv_bfloat162 h1 = __floats2bfloat162_rn(v10, v11);
                __nv_bfloat162 l0 = __floats2bfloat162_rn(v00 - __low2float(h0), v01 - __high2float(h0));
                __nv_bfloat162 l1 = __floats2bfloat162_rn(v10 - __low2float(h1), v11 - __high2float(h1));
                if (which == 2) {
                    size_t vb = (size_t)head * (HD * N_TOK);
                    g_Vth[vb + (size_t)eh * N_TOK + m]           = h0.x;
                    g_Vth[vb + (size_t)(eh + 1) * N_TOK + m]     = h0.y;
                    g_Vth[vb + (size_t)eh * N_TOK + m + 8]       = h1.x;
                    g_Vth[vb + (size_t)(eh + 1) * N_TOK + m + 8] = h1.y;
                    g_Vtl[vb + (size_t)eh * N_TOK + m]           = l0.x;
                    g_Vtl[vb + (size_t)(eh + 1) * N_TOK + m]     = l0.y;
                    g_Vtl[vb + (size_t)eh * N_TOK + m + 8]       = l1.x;
                    g_Vtl[vb + (size_t)(eh + 1) * N_TOK + m + 8] = l1.y;
                } else {
                    __nv_bfloat16* dh = (which == 0) ? g_Qh : g_Kh;
                    __nv_bfloat16* dl = (which == 0) ? g_Ql : g_Kl;
                    size_t b0 = (size_t)head * (N_TOK * HD) + (size_t)m * HD + eh;
                    size_t b1 = b0 + 8 * HD;
                    *(__nv_bfloat162*)(dh + b0) = h0;
                    *(__nv_bfloat162*)(dh + b1) = h1;
                    *(__nv_bfloat162*)(dl + b0) = l0;
                    *(__nv_bfloat162*)(dl + b1) = l1;
                }
            }
        }
    } else {
#pragma unroll
        for (int mt = 0; mt < 4; mt++) {
            int m = row0 + wm * 64 + mt * 16 + g;
#pragma unroll
            for (int nt = 0; nt < 4; nt++) {
                int e = col0 + wn * 32 + nt * 8 + 2 * tig;
                float2 b = *(const float2*)(bo + e);
                *(float2*)(out + (size_t)m * D_MODEL + e) =
                    make_float2(acc[mt][nt][0] + b.x, acc[mt][nt][1] + b.y);
                *(float2*)(out + (size_t)(m + 8) * D_MODEL + e) =
                    make_float2(acc[mt][nt][2] + b.x, acc[mt][nt][3] + b.y);
            }
        }
    }
}

// ---------------------------------------------------------------------------
// Tensor-core causal flash attention, 3-stage cp.async pipeline, ONE sync/iter.
// CTA = 128 q x 128 k, 8 warps x 16 rows; softmax in registers (base-2).
// grid = (NH, 32 tiles), qt = 31 - blockIdx.y  => global longest-first order.
// ---------------------------------------------------------------------------
#define AT_KSTR 72
#define AT_VSTR 136
#define AT_KBYTES (128 * AT_KSTR * 2)    // 18432
#define AT_VBYTES (64 * AT_VSTR * 2)     // 17408
#define AT_STAGE  (2 * AT_KBYTES + 2 * AT_VBYTES)  // 71680
#define AT_SMEM   (3 * AT_STAGE)                    // 215040

__global__ __launch_bounds__(256, 1) void attn_mma() {
    extern __shared__ char sma[];
    const uint32_t sbase = smem_u32(sma);

    const int h  = blockIdx.x;
    const int qt = (int)(gridDim.y - 1 - blockIdx.y);  // global longest-first
    const int q0 = qt * 128;
    const int t = threadIdx.x, wid = t >> 5, lane = t & 31;
    const int g = lane >> 2, tig = lane & 3;

    const __nv_bfloat16* Qh_g = g_Qh + (size_t)h * (N_TOK * HD);
    const __nv_bfloat16* Ql_g = g_Ql + (size_t)h * (N_TOK * HD);
    const __nv_bfloat16* Kh_g = g_Kh + (size_t)h * (N_TOK * HD);
    const __nv_bfloat16* Kl_g = g_Kl + (size_t)h * (N_TOK * HD);
    const __nv_bfloat16* Vh_g = g_Vth + (size_t)h * (HD * N_TOK);
    const __nv_bfloat16* Vl_g = g_Vtl + (size_t)h * (HD * N_TOK);

    auto issue_kv = [&](int kt, int stage) {
        const int k0 = kt * 128;
        uint32_t sb = sbase + stage * AT_STAGE;
#pragma unroll
        for (int i = 0; i < 4; i++) {
            int idx = t + 256 * i;
            int r = idx >> 3, c8 = (idx & 7) * 8;
            uint32_t so = (uint32_t)(r * AT_KSTR + c8) * 2;
            cp16(sb + so,             Kh_g + (size_t)(k0 + r) * HD + c8);
            cp16(sb + AT_KBYTES + so, Kl_g + (size_t)(k0 + r) * HD + c8);
        }
#pragma unroll
        for (int i = 0; i < 4; i++) {
            int idx = t + 256 * i;
            int r = idx >> 4, c8 = (idx & 15) * 8;
            uint32_t so = (uint32_t)(r * AT_VSTR + c8) * 2;
            cp16(sb + 2 * AT_KBYTES + so,             Vh_g + (size_t)r * N_TOK + k0 + c8);
            cp16(sb + 2 * AT_KBYTES + AT_VBYTES + so, Vl_g + (size_t)r * N_TOK + k0 + c8);
        }
        CP_COMMIT();
    };

    // Prologue: keep exactly 2 groups in flight (duplicates beyond qt are
    // written to stages that are never read).
    issue_kv(0, 0);
    issue_kv(qt >= 1 ? 1 : 0, 1);

    const int qrow = q0 + wid * 16 + g;

    // Preload Q fragments (already scaled by log2e/8 at projection time)
    uint32_t qfh[4][4], qfl[4][4];
#pragma unroll
    for (int ks = 0; ks < 4; ks++) {
        int c = ks * 16 + 2 * tig;
        qfh[ks][0] = *(const uint32_t*)(Qh_g + (size_t)qrow * HD + c);
        qfh[ks][1] = *(const uint32_t*)(Qh_g + (size_t)(qrow + 8) * HD + c);
        qfh[ks][2] = *(const uint32_t*)(Qh_g + (size_t)qrow * HD + c + 8);
        qfh[ks][3] = *(const uint32_t*)(Qh_g + (size_t)(qrow + 8) * HD + c + 8);
        qfl[ks][0] = *(const uint32_t*)(Ql_g + (size_t)qrow * HD + c);
        qfl[ks][1] = *(const uint32_t*)(Ql_g + (size_t)(qrow + 8) * HD + c);
        qfl[ks][2] = *(const uint32_t*)(Ql_g + (size_t)qrow * HD + c + 8);
        qfl[ks][3] = *(const uint32_t*)(Ql_g + (size_t)(qrow + 8) * HD + c + 8);
    }

    const int rofs = (lane & 7) + ((lane & 16) >> 1);
    const int cofs = (lane & 8);
    const uint32_t kofs = (uint32_t)(rofs * AT_KSTR + cofs) * 2;
    const uint32_t vofs = (uint32_t)(rofs * AT_VSTR + cofs) * 2;

    float m0 = -1e30f, m1 = -1e30f, l0 = 0.0f, l1 = 0.0f;
    float o[8][4] = {};

    int stage = 0;
    for (int kt = 0; kt <= qt; kt++) {
        CP_WAIT1();          // stage `stage` (tile kt) is complete
        __syncthreads();     // all warps done with the stage being overwritten next
        {
            int nxt = kt + 2;
            issue_kv(nxt <= qt ? nxt : qt, (stage + 2) % 3);
        }

        const uint32_t sb = sbase + stage * AT_STAGE;
        const uint32_t kb_h = sb + kofs;
        const uint32_t kb_l = sb + AT_KBYTES + kofs;
        const uint32_t vb_h = sb + 2 * AT_KBYTES + vofs;
        const uint32_t vb_l = sb + 2 * AT_KBYTES + AT_VBYTES + vofs;
        const int k0 = kt * 128;
        stage = (stage + 1) % 3;

        // S = Q K^T
        float s[16][4];
#pragma unroll
        for (int nt = 0; nt < 16; nt++) { s[nt][0] = s[nt][1] = s[nt][2] = s[nt][3] = 0.0f; }
#pragma unroll
        for (int ks = 0; ks < 4; ks++) {
#pragma unroll
            for (int ntp = 0; ntp < 8; ntp++) {
                uint32_t bh[4], bl[4];
                uint32_t off = (uint32_t)(ntp * 16 * AT_KSTR + ks * 16) * 2;
                ldsm_x4(bh, kb_h + off);
                ldsm_x4(bl, kb_l + off);
                mma_bf16(s[2 * ntp],     qfh[ks], bh);
                mma_bf16(s[2 * ntp],     qfh[ks], bl);
                mma_bf16(s[2 * ntp],     qfl[ks], bh);
                mma_bf16(s[2 * ntp + 1], qfh[ks], bh + 2);
                mma_bf16(s[2 * ntp + 1], qfh[ks], bl + 2);
                mma_bf16(s[2 * ntp + 1], qfl[ks], bh + 2);
            }
        }

        if (kt == qt) {   // causal mask on diagonal tile
#pragma unroll
            for (int nt = 0; nt < 16; nt++) {
                int c = k0 + nt * 8 + 2 * tig;
                if (c     > qrow)     s[nt][0] = -1e30f;
                if (c + 1 > qrow)     s[nt][1] = -1e30f;
                if (c     > qrow + 8) s[nt][2] = -1e30f;
                if (c + 1 > qrow + 8) s[nt][3] = -1e30f;
            }
        }

        // Online softmax in base-2 (registers + shfl over 4 tig lanes)
        float mx0 = -1e30f, mx1 = -1e30f;
#pragma unroll
        for (int nt = 0; nt < 16; nt++) {
            mx0 = fmaxf(mx0, fmaxf(s[nt][0], s[nt][1]));
            mx1 = fmaxf(mx1, fmaxf(s[nt][2], s[nt][3]));
        }
        mx0 = fmaxf(mx0, __shfl_xor_sync(0xffffffffu, mx0, 1));
        mx0 = fmaxf(mx0, __shfl_xor_sync(0xffffffffu, mx0, 2));
        mx1 = fmaxf(mx1, __shfl_xor_sync(0xffffffffu, mx1, 1));
        mx1 = fmaxf(mx1, __shfl_xor_sync(0xffffffffu, mx1, 2));
        float mn0 = fmaxf(m0, mx0), mn1 = fmaxf(m1, mx1);
        float a0 = fast_exp2(m0 - mn0), a1 = fast_exp2(m1 - mn1);
        m0 = mn0; m1 = mn1;
        float sum0 = 0.0f, sum1 = 0.0f;
#pragma unroll
        for (int nt = 0; nt < 16; nt++) {
            s[nt][0] = fast_exp2(s[nt][0] - mn0);
            s[nt][1] = fast_exp2(s[nt][1] - mn0);
            s[nt][2] = fast_exp2(s[nt][2] - mn1);
            s[nt][3] = fast_exp2(s[nt][3] - mn1);
            sum0 += s[nt][0] + s[nt][1];
            sum1 += s[nt][2] + s[nt][3];
        }
        sum0 += __shfl_xor_sync(0xffffffffu, sum0, 1);
        sum0 += __shfl_xor_sync(0xffffffffu, sum0, 2);
        sum1 += __shfl_xor_sync(0xffffffffu, sum1, 1);
        sum1 += __shfl_xor_sync(0xffffffffu, sum1, 2);
        l0 = l0 * a0 + sum0;
        l1 = l1 * a1 + sum1;
#pragma unroll
        for (int f = 0; f < 8; f++) {
            o[f][0] *= a0; o[f][1] *= a0; o[f][2] *= a1; o[f][3] *= a1;
        }

        // O += P V  (P split hi/lo in registers; V via ldmatrix)
#pragma unroll
        for (int kk = 0; kk < 8; kk++) {
            uint32_t ph[4], pl[4];
            {
                __nv_bfloat162 t0 = __floats2bfloat162_rn(s[2 * kk][0], s[2 * kk][1]);
                __nv_bfloat162 t1 = __floats2bfloat162_rn(s[2 * kk][2], s[2 * kk][3]);
                __nv_bfloat162 t2 = __floats2bfloat162_rn(s[2 * kk + 1][0], s[2 * kk + 1][1]);
                __nv_bfloat162 t3 = __floats2bfloat162_rn(s[2 * kk + 1][2], s[2 * kk + 1][3]);
                ph[0] = *(uint32_t*)&t0; ph[1] = *(uint32_t*)&t1;
                ph[2] = *(uint32_t*)&t2; ph[3] = *(uint32_t*)&t3;
                __nv_bfloat162 u0 = __floats2bfloat162_rn(s[2 * kk][0] - __low2float(t0),
                                                          s[2 * kk][1] - __high2float(t0));
                __nv_bfloat162 u1 = __floats2bfloat162_rn(s[2 * kk][2] - __low2float(t1),
                                                          s[2 * kk][3] - __high2float(t1));
                __nv_bfloat162 u2 = __floats2bfloat162_rn(s[2 * kk + 1][0] - __low2float(t2),
                                                          s[2 * kk + 1][1] - __high2float(t2));
                __nv_bfloat162 u3 = __floats2bfloat162_rn(s[2 * kk + 1][2] - __low2float(t3),
                                                          s[2 * kk + 1][3] - __high2float(t3));
                pl[0] = *(uint32_t*)&u0; pl[1] = *(uint32_t*)&u1;
                pl[2] = *(uint32_t*)&u2; pl[3] = *(uint32_t*)&u3;
            }
#pragma unroll
            for (int dtp = 0; dtp < 4; dtp++) {
                uint32_t bh[4], bl[4];
                uint32_t off = (uint32_t)(dtp * 16 * AT_VSTR + kk * 16) * 2;
                ldsm_x4(bh, vb_h + off);
                ldsm_x4(bl, vb_l + off);
                mma_bf16(o[2 * dtp],     ph, bh);
                mma_bf16(o[2 * dtp],     ph, bl);
                mma_bf16(o[2 * dtp],     pl, bh);
                mma_bf16(o[2 * dtp + 1], ph, bh + 2);
                mma_bf16(o[2 * dtp + 1], ph, bl + 2);
                mma_bf16(o[2 * dtp + 1], pl, bh + 2);
            }
        }
    }
    CP_WAIT0();   // drain outstanding prefetches before exit

    // Epilogue: normalize, split to bf16 hi/lo, write ctx head-major.
    float i0 = 1.0f / l0, i1 = 1.0f / l1;
#pragma unroll
    for (int f = 0; f < 8; f++) {
        int d = f * 8 + 2 * tig;
        float v00 = o[f][0] * i0, v01 = o[f][1] * i0;
        float v10 = o[f][2] * i1, v11 = o[f][3] * i1;
        __nv_bfloat162 h0 = __floats2bfloat162_rn(v00, v01);
        __nv_bfloat162 h1 = __floats2bfloat162_rn(v10, v11);
        __nv_bfloat162 e0 = __floats2bfloat162_rn(v00 - __low2float(h0), v01 - __high2float(h0));
        __nv_bfloat162 e1 = __floats2bfloat162_rn(v10 - __low2float(h1), v11 - __high2float(h1));
        size_t b0 = (size_t)h * (N_TOK * HD) + (size_t)qrow * HD + d;
        size_t b1 = b0 + 8 * HD;
        *(__nv_bfloat162*)(g_C_hi + b0) = h0;
        *(__nv_bfloat162*)(g_C_hi + b1) = h1;
        *(__nv_bfloat162*)(g_C_lo + b0) = e0;
        *(__nv_bfloat162*)(g_C_lo + b1) = e1;
    }
}

extern "C" void kernel_launch(void* const* d_in, const int* in_sizes, int n_in,
                              void* d_out, int out_size) {
    const float* x  = (const float*)d_in[0];
    const float* Wq = (const float*)d_in[1];
    const float* Wk = (const float*)d_in[2];
    const float* Wv = (const float*)d_in[3];
    const float* Wo = (const float*)d_in[4];
    const float* bo = (const float*)d_in[5];
    float* out = (float*)d_out;

    cudaFuncSetAttribute(attn_mma, cudaFuncAttributeMaxDynamicSharedMemorySize, AT_SMEM);
    cudaFuncSetAttribute(mma_gemm, cudaFuncAttributeMaxDynamicSharedMemorySize, G_SMEM);

    split_x<<<(N_TOK * D_MODEL / 4) / 256, 256>>>(x);
    wprep<<<dim3(32, 32, 4), dim3(32, 8)>>>(Wq, Wk, Wv, Wo);
    mma_gemm<<<dim3(8, 32, 3), 256, G_SMEM>>>(0, nullptr, nullptr);
    attn_mma<<<dim3(NH, N_TOK / 128), 256, AT_SMEM>>>();
    mma_gemm<<<dim3(8, 32, 1), 256, G_SMEM>>>(1, out, bo);
}

// round 10
// speedup vs baseline: 2.4108x; 1.0032x over previous
#include <cuda_runtime.h>
#include <cuda_bf16.h>
#include <cstdint>

#define N_TOK 4096
#define D_MODEL 1024
#define NH 16
#define HD 64

// ---------------------------------------------------------------------------
// Scratch (__device__ globals — no allocation).
// ---------------------------------------------------------------------------
__device__ __nv_bfloat16 g_x_hi[N_TOK * D_MODEL];
__device__ __nv_bfloat16 g_x_lo[N_TOK * D_MODEL];
__device__ __nv_bfloat16 g_WT_hi[4 * D_MODEL * D_MODEL];  // [which][e][k]
__device__ __nv_bfloat16 g_WT_lo[4 * D_MODEL * D_MODEL];
__device__ __nv_bfloat16 g_Qh[NH * N_TOK * HD];            // [h][tok][d], scaled log2e/8
__device__ __nv_bfloat16 g_Ql[NH * N_TOK * HD];
__device__ __nv_bfloat16 g_Kh[NH * N_TOK * HD];            // [h][tok][d]
__device__ __nv_bfloat16 g_Kl[NH * N_TOK * HD];
__device__ __nv_bfloat16 g_Vth[NH * HD * N_TOK];           // [h][d][tok] (transposed)
__device__ __nv_bfloat16 g_Vtl[NH * HD * N_TOK];
__device__ __nv_bfloat16 g_C_hi[NH * N_TOK * HD];          // ctx head-major
__device__ __nv_bfloat16 g_C_lo[NH * N_TOK * HD];

// HMMA m16n8k16 bf16 -> f32 accum (baseline PTX, works on sm_103 target)
__device__ __forceinline__ void mma_bf16(float* d, const uint32_t* a, const uint32_t* b) {
    asm volatile(
        "mma.sync.aligned.m16n8k16.row.col.f32.bf16.bf16.f32 "
        "{%0,%1,%2,%3}, {%4,%5,%6,%7}, {%8,%9}, {%0,%1,%2,%3};"
        : "+f"(d[0]), "+f"(d[1]), "+f"(d[2]), "+f"(d[3])
        : "r"(a[0]), "r"(a[1]), "r"(a[2]), "r"(a[3]), "r"(b[0]), "r"(b[1]));
}

__device__ __forceinline__ void ldsm_x4(uint32_t* r, uint32_t addr) {
    asm volatile("ldmatrix.sync.aligned.m8n8.x4.shared.b16 {%0,%1,%2,%3}, [%4];"
                 : "=r"(r[0]), "=r"(r[1]), "=r"(r[2]), "=r"(r[3]) : "r"(addr));
}

__device__ __forceinline__ uint32_t smem_u32(const void* p) {
    uint32_t a;
    asm("{ .reg .u64 t; cvta.to.shared.u64 t, %1; cvt.u32.u64 %0, t; }" : "=r"(a) : "l"(p));
    return a;
}

__device__ __forceinline__ void cp16(uint32_t saddr, const void* g) {
    asm volatile("cp.async.cg.shared.global [%0], [%1], 16;" :: "r"(saddr), "l"(g));
}
#define CP_COMMIT() asm volatile("cp.async.commit_group;" ::: "memory")
#define CP_WAIT0()  asm volatile("cp.async.wait_group 0;" ::: "memory")
#define CP_WAIT1()  asm volatile("cp.async.wait_group 1;" ::: "memory")

// Fast 2^y on the FMA pipe (no MUFU). rel err ~3e-6.
__device__ __forceinline__ float fast_exp2(float y) {
    y = fmaxf(y, -126.0f);
    float t = y + 12582912.0f;                       // 1.5 * 2^23
    int   i = __float_as_int(t) - 0x4B400000;
    float f = y - (t - 12582912.0f);                 // f in [-0.5, 0.5]
    float p =            1.3333558146e-3f;
    p = fmaf(p, f, 9.6181291057e-3f);
    p = fmaf(p, f, 5.5504108664e-2f);
    p = fmaf(p, f, 2.4022650696e-1f);
    p = fmaf(p, f, 6.9314718056e-1f);
    p = fmaf(p, f, 1.0f);
    return __int_as_float(__float_as_int(p) + (i << 23));
}

// ---------------------------------------------------------------------------
// Prep: split x into bf16 hi/lo (K-major, same layout as x).
// ---------------------------------------------------------------------------
__global__ __launch_bounds__(256) void split_x(const float* __restrict__ x) {
    int idx = blockIdx.x * 256 + threadIdx.x;
    float4 v = ((const float4*)x)[idx];
    __nv_bfloat162 h0 = __floats2bfloat162_rn(v.x, v.y);
    __nv_bfloat162 h1 = __floats2bfloat162_rn(v.z, v.w);
    float l0 = v.x - __low2float(h0), l1 = v.y - __high2float(h0);
    float l2 = v.z - __low2float(h1), l3 = v.w - __high2float(h1);
    ((__nv_bfloat162*)g_x_hi)[idx * 2]     = h0;
    ((__nv_bfloat162*)g_x_hi)[idx * 2 + 1] = h1;
    ((__nv_bfloat162*)g_x_lo)[idx * 2]     = __floats2bfloat162_rn(l0, l1);
    ((__nv_bfloat162*)g_x_lo)[idx * 2 + 1] = __floats2bfloat162_rn(l2, l3);
}

// ---------------------------------------------------------------------------
// Prep: WT[which][e][k] = W[k][e], split into bf16 hi/lo. 32x32 smem transpose.
// ---------------------------------------------------------------------------
__global__ void wprep(const float* __restrict__ Wq, const float* __restrict__ Wk,
                      const float* __restrict__ Wv, const float* __restrict__ Wo) {
    const int z = blockIdx.z;
    const float* W = (z == 0) ? Wq : (z == 1) ? Wk : (z == 2) ? Wv : Wo;
    __shared__ float ts[32][33];
    const int e0 = blockIdx.x * 32, k0 = blockIdx.y * 32;
    const int tx = threadIdx.x, ty = threadIdx.y;  // (32, 8)
#pragma unroll
    for (int i = 0; i < 4; i++)
        ts[ty + 8 * i][tx] = W[(size_t)(k0 + ty + 8 * i) * D_MODEL + e0 + tx];
    __syncthreads();
#pragma unroll
    for (int i = 0; i < 4; i++) {
        int row = ty + 8 * i;
        float v = ts[tx][row];
        __nv_bfloat16 hi = __float2bfloat16(v);
        float lo = v - __bfloat162float(hi);
        size_t o = (size_t)z * (D_MODEL * D_MODEL) + (size_t)(e0 + row) * D_MODEL + k0 + tx;
        g_WT_hi[o] = hi;
        g_WT_lo[o] = __float2bfloat16(lo);
    }
}

// ---------------------------------------------------------------------------
// HMMA bf16-split GEMM, cp.async double-buffered, ldmatrix fragment loads.
// mode 0: qkv — epilogue splits hi/lo: Q (scaled log2e/8) & K row-major,
//         V transposed [h][d][tok].
// mode 1: oproj (A = ctx hi/lo head-major; out = d_out + bias, fp32)
// ---------------------------------------------------------------------------
#define KC 32
#define ASTR 40
#define G_TILE  (128 * ASTR * 2)        // 10240 B per tile
#define G_STAGE (4 * G_TILE)            // 40960 B per stage
#define G_SMEM  (2 * G_STAGE)           // 81920 B

__global__ __launch_bounds__(256, 2) void mma_gemm(int mode, float* __restrict__ out,
                                                   const float* __restrict__ bo) {
    extern __shared__ char smc[];
    const uint32_t sbase = smem_u32(smc);

    const int t = threadIdx.x;
    const int wid = t >> 5, lane = t & 31;
    const int wm = wid & 1, wn = wid >> 1;
    const int g = lane >> 2, tig = lane & 3;
    const int row0 = blockIdx.y * 128;
    const int col0 = blockIdx.x * 128;
    const int which = (mode == 0) ? blockIdx.z : 3;

    const __nv_bfloat16* Bh_g = g_WT_hi + (size_t)which * (D_MODEL * D_MODEL) + (size_t)col0 * D_MODEL;
    const __nv_bfloat16* Bl_g = g_WT_lo + (size_t)which * (D_MODEL * D_MODEL) + (size_t)col0 * D_MODEL;

    const int ld_r = t >> 2, ld_c = (t & 3) * 8;     // each thread: 2 rows x 8 bf16

    auto issue_chunk = [&](int kc) {
        const int k0 = kc * KC;
        const __nv_bfloat16 *Ah_g, *Al_g;
        int astr;
        if (mode == 0) {
            Ah_g = g_x_hi + (size_t)row0 * D_MODEL + k0;
            Al_g = g_x_lo + (size_t)row0 * D_MODEL + k0;
            astr = D_MODEL;
        } else {
            size_t base = (size_t)(k0 >> 6) * (N_TOK * HD) + (size_t)row0 * HD + (k0 & 63);
            Ah_g = g_C_hi + base;
            Al_g = g_C_lo + base;
            astr = HD;
        }
        uint32_t sb = sbase + (kc & 1) * G_STAGE;
#pragma unroll
        for (int i = 0; i < 2; i++) {
            int r = ld_r + 64 * i;
            uint32_t so = (uint32_t)(r * ASTR + ld_c) * 2;
            cp16(sb + so,              Ah_g + (size_t)r * astr + ld_c);
            cp16(sb + G_TILE + so,     Al_g + (size_t)r * astr + ld_c);
            cp16(sb + 2 * G_TILE + so, Bh_g + (size_t)r * D_MODEL + k0 + ld_c);
            cp16(sb + 3 * G_TILE + so, Bl_g + (size_t)r * D_MODEL + k0 + ld_c);
        }
        CP_COMMIT();
    };

    // ldmatrix lane offsets.
    const int arofs = (lane & 7) + (lane & 8);
    const int acofs = (lane & 16) >> 1;
    const int brofs = (lane & 7) + ((lane & 16) >> 1);
    const int bcofs = (lane & 8);

    float acc[4][4][4] = {};

    issue_chunk(0);
    for (int kc = 0; kc < D_MODEL / KC; kc++) {
        CP_WAIT0();
        __syncthreads();   // single sync per iter: protects stage reuse + visibility
        if (kc + 1 < D_MODEL / KC) issue_chunk(kc + 1);

        const uint32_t st = sbase + (kc & 1) * G_STAGE;
        const uint32_t sAh = st;
        const uint32_t sAl = st + G_TILE;
        const uint32_t sBh = st + 2 * G_TILE;
        const uint32_t sBl = st + 3 * G_TILE;

#pragma unroll
        for (int ks = 0; ks < KC; ks += 16) {
            uint32_t bh[4][2], bl[4][2];
#pragma unroll
            for (int p = 0; p < 2; p++) {
                uint32_t off = (uint32_t)((wn * 32 + p * 16 + brofs) * ASTR + ks + bcofs) * 2;
                uint32_t rb[4];
                ldsm_x4(rb, sBh + off);
                bh[2 * p][0] = rb[0]; bh[2 * p][1] = rb[1];
                bh[2 * p + 1][0] = rb[2]; bh[2 * p + 1][1] = rb[3];
                ldsm_x4(rb, sBl + off);
                bl[2 * p][0] = rb[0]; bl[2 * p][1] = rb[1];
                bl[2 * p + 1][0] = rb[2]; bl[2 * p + 1][1] = rb[3];
            }
#pragma unroll
            for (int mt = 0; mt < 4; mt++) {
                uint32_t off = (uint32_t)((wm * 64 + mt * 16 + arofs) * ASTR + ks + acofs) * 2;
                uint32_t ah[4], al[4];
                ldsm_x4(ah, sAh + off);
                ldsm_x4(al, sAl + off);
#pragma unroll
                for (int nt = 0; nt < 4; nt++) {
                    mma_bf16(acc[mt][nt], ah, bh[nt]);
                    mma_bf16(acc[mt][nt], ah, bl[nt]);
                    mma_bf16(acc[mt][nt], al, bh[nt]);
                }
            }
        }
    }

    if (mode == 0) {
        const int head = (col0 + wn * 32) >> 6;
        // fold 1/sqrt(64) * log2(e) into Q (softmax runs in base-2 domain)
        const float sc = (which == 0) ? 0.125f * 1.4426950408889634f : 1.0f;
#pragma unroll
        for (int mt = 0; mt < 4; mt++) {
            int m = row0 + wm * 64 + mt * 16 + g;
#pragma unroll
            for (int nt = 0; nt < 4; nt++) {
                int eh = (wn * 32 + nt * 8 + 2 * tig) & 63;
                float v00 = acc[mt][nt][0] * sc, v01 = acc[mt][nt][1] * sc;
                float v10 = acc[mt][nt][2] * sc, v11 = acc[mt][nt][3] * sc;
                __nv_bfloat162 h0 = __floats2bfloat162_rn(v00, v01);
                __nv_bfloat162 h1 = __floats2bfloat162_rn(v10, v11);
                __nv_bfloat162 l0 = __floats2bfloat162_rn(v00 - __low2float(h0), v01 - __high2float(h0));
                __nv_bfloat162 l1 = __floats2bfloat162_rn(v10 - __low2float(h1), v11 - __high2float(h1));
                if (which == 2) {
                    size_t vb = (size_t)head * (HD * N_TOK);
                    g_Vth[vb + (size_t)eh * N_TOK + m]           = h0.x;
                    g_Vth[vb + (size_t)(eh + 1) * N_TOK + m]     = h0.y;
                    g_Vth[vb + (size_t)eh * N_TOK + m + 8]       = h1.x;
                    g_Vth[vb + (size_t)(eh + 1) * N_TOK + m + 8] = h1.y;
                    g_Vtl[vb + (size_t)eh * N_TOK + m]           = l0.x;
                    g_Vtl[vb + (size_t)(eh + 1) * N_TOK + m]     = l0.y;
                    g_Vtl[vb + (size_t)eh * N_TOK + m + 8]       = l1.x;
                    g_Vtl[vb + (size_t)(eh + 1) * N_TOK + m + 8] = l1.y;
                } else {
                    __nv_bfloat16* dh = (which == 0) ? g_Qh : g_Kh;
                    __nv_bfloat16* dl = (which == 0) ? g_Ql : g_Kl;
                    size_t b0 = (size_t)head * (N_TOK * HD) + (size_t)m * HD + eh;
                    size_t b1 = b0 + 8 * HD;
                    *(__nv_bfloat162*)(dh + b0) = h0;
                    *(__nv_bfloat162*)(dh + b1) = h1;
                    *(__nv_bfloat162*)(dl + b0) = l0;
                    *(__nv_bfloat162*)(dl + b1) = l1;
                }
            }
        }
    } else {
#pragma unroll
        for (int mt = 0; mt < 4; mt++) {
            int m = row0 + wm * 64 + mt * 16 + g;
#pragma unroll
            for (int nt = 0; nt < 4; nt++) {
                int e = col0 + wn * 32 + nt * 8 + 2 * tig;
                float2 b = *(const float2*)(bo + e);
                *(float2*)(out + (size_t)m * D_MODEL + e) =
                    make_float2(acc[mt][nt][0] + b.x, acc[mt][nt][1] + b.y);
                *(float2*)(out + (size_t)(m + 8) * D_MODEL + e) =
                    make_float2(acc[mt][nt][2] + b.x, acc[mt][nt][3] + b.y);
            }
        }
    }
}

// ---------------------------------------------------------------------------
// Tensor-core causal flash attention, 3-stage cp.async pipeline, ONE sync/iter.
// Softmax fused per-chunk into the PV MMA stream (exp/cvt overlap tensor pipe).
// grid = (NH, 32 tiles), qt = 31 - blockIdx.y  => global longest-first order.
// ---------------------------------------------------------------------------
#define AT_KSTR 72
#define AT_VSTR 136
#define AT_KBYTES (128 * AT_KSTR * 2)    // 18432
#define AT_VBYTES (64 * AT_VSTR * 2)     // 17408
#define AT_STAGE  (2 * AT_KBYTES + 2 * AT_VBYTES)  // 71680
#define AT_SMEM   (3 * AT_STAGE)                    // 215040

__global__ __launch_bounds__(256, 1) void attn_mma() {
    extern __shared__ char sma[];
    const uint32_t sbase = smem_u32(sma);

    const int h  = blockIdx.x;
    const int qt = (int)(gridDim.y - 1 - blockIdx.y);  // global longest-first
    const int q0 = qt * 128;
    const int t = threadIdx.x, wid = t >> 5, lane = t & 31;
    const int g = lane >> 2, tig = lane & 3;

    const __nv_bfloat16* Qh_g = g_Qh + (size_t)h * (N_TOK * HD);
    const __nv_bfloat16* Ql_g = g_Ql + (size_t)h * (N_TOK * HD);
    const __nv_bfloat16* Kh_g = g_Kh + (size_t)h * (N_TOK * HD);
    const __nv_bfloat16* Kl_g = g_Kl + (size_t)h * (N_TOK * HD);
    const __nv_bfloat16* Vh_g = g_Vth + (size_t)h * (HD * N_TOK);
    const __nv_bfloat16* Vl_g = g_Vtl + (size_t)h * (HD * N_TOK);

    auto issue_kv = [&](int kt, int stage) {
        const int k0 = kt * 128;
        uint32_t sb = sbase + stage * AT_STAGE;
#pragma unroll
        for (int i = 0; i < 4; i++) {
            int idx = t + 256 * i;
            int r = idx >> 3, c8 = (idx & 7) * 8;
            uint32_t so = (uint32_t)(r * AT_KSTR + c8) * 2;
            cp16(sb + so,             Kh_g + (size_t)(k0 + r) * HD + c8);
            cp16(sb + AT_KBYTES + so, Kl_g + (size_t)(k0 + r) * HD + c8);
        }
#pragma unroll
        for (int i = 0; i < 4; i++) {
            int idx = t + 256 * i;
            int r = idx >> 4, c8 = (idx & 15) * 8;
            uint32_t so = (uint32_t)(r * AT_VSTR + c8) * 2;
            cp16(sb + 2 * AT_KBYTES + so,             Vh_g + (size_t)r * N_TOK + k0 + c8);
            cp16(sb + 2 * AT_KBYTES + AT_VBYTES + so, Vl_g + (size_t)r * N_TOK + k0 + c8);
        }
        CP_COMMIT();
    };

    // Prologue: keep exactly 2 groups in flight.
    issue_kv(0, 0);
    issue_kv(qt >= 1 ? 1 : 0, 1);

    const int qrow = q0 + wid * 16 + g;

    // Preload Q fragments (already scaled by log2e/8 at projection time)
    uint32_t qfh[4][4], qfl[4][4];
#pragma unroll
    for (int ks = 0; ks < 4; ks++) {
        int c = ks * 16 + 2 * tig;
        qfh[ks][0] = *(const uint32_t*)(Qh_g + (size_t)qrow * HD + c);
        qfh[ks][1] = *(const uint32_t*)(Qh_g + (size_t)(qrow + 8) * HD + c);
        qfh[ks][2] = *(const uint32_t*)(Qh_g + (size_t)qrow * HD + c + 8);
        qfh[ks][3] = *(const uint32_t*)(Qh_g + (size_t)(qrow + 8) * HD + c + 8);
        qfl[ks][0] = *(const uint32_t*)(Ql_g + (size_t)qrow * HD + c);
        qfl[ks][1] = *(const uint32_t*)(Ql_g + (size_t)(qrow + 8) * HD + c);
        qfl[ks][2] = *(const uint32_t*)(Ql_g + (size_t)qrow * HD + c + 8);
        qfl[ks][3] = *(const uint32_t*)(Ql_g + (size_t)(qrow + 8) * HD + c + 8);
    }

    const int rofs = (lane & 7) + ((lane & 16) >> 1);
    const int cofs = (lane & 8);
    const uint32_t kofs = (uint32_t)(rofs * AT_KSTR + cofs) * 2;
    const uint32_t vofs = (uint32_t)(rofs * AT_VSTR + cofs) * 2;

    float m0 = -1e30f, m1 = -1e30f, l0 = 0.0f, l1 = 0.0f;
    float o[8][4] = {};

    int stage = 0;
    for (int kt = 0; kt <= qt; kt++) {
        CP_WAIT1();          // stage `stage` (tile kt) is complete
        __syncthreads();     // all warps done with the stage being overwritten next
        {
            int nxt = kt + 2;
            issue_kv(nxt <= qt ? nxt : qt, (stage + 2) % 3);
        }

        const uint32_t sb = sbase + stage * AT_STAGE;
        const uint32_t kb_h = sb + kofs;
        const uint32_t kb_l = sb + AT_KBYTES + kofs;
        const uint32_t vb_h = sb + 2 * AT_KBYTES + vofs;
        const uint32_t vb_l = sb + 2 * AT_KBYTES + AT_VBYTES + vofs;
        const int k0 = kt * 128;
        stage = (stage + 1) % 3;

        // S = Q K^T
        float s[16][4];
#pragma unroll
        for (int nt = 0; nt < 16; nt++) { s[nt][0] = s[nt][1] = s[nt][2] = s[nt][3] = 0.0f; }
#pragma unroll
        for (int ks = 0; ks < 4; ks++) {
#pragma unroll
            for (int ntp = 0; ntp < 8; ntp++) {
                uint32_t bh[4], bl[4];
                uint32_t off = (uint32_t)(ntp * 16 * AT_KSTR + ks * 16) * 2;
                ldsm_x4(bh, kb_h + off);
                ldsm_x4(bl, kb_l + off);
                mma_bf16(s[2 * ntp],     qfh[ks], bh);
                mma_bf16(s[2 * ntp],     qfh[ks], bl);
                mma_bf16(s[2 * ntp],     qfl[ks], bh);
                mma_bf16(s[2 * ntp + 1], qfh[ks], bh + 2);
                mma_bf16(s[2 * ntp + 1], qfh[ks], bl + 2);
                mma_bf16(s[2 * ntp + 1], qfl[ks], bh + 2);
            }
        }

        if (kt == qt) {   // causal mask on diagonal tile
#pragma unroll
            for (int nt = 0; nt < 16; nt++) {
                int c = k0 + nt * 8 + 2 * tig;
                if (c     > qrow)     s[nt][0] = -1e30f;
                if (c + 1 > qrow)     s[nt][1] = -1e30f;
                if (c     > qrow + 8) s[nt][2] = -1e30f;
                if (c + 1 > qrow + 8) s[nt][3] = -1e30f;
            }
        }

        // Row max (the only true serial point before PV)
        float mx0 = -1e30f, mx1 = -1e30f;
#pragma unroll
        for (int nt = 0; nt < 16; nt++) {
            mx0 = fmaxf(mx0, fmaxf(s[nt][0], s[nt][1]));
            mx1 = fmaxf(mx1, fmaxf(s[nt][2], s[nt][3]));
        }
        mx0 = fmaxf(mx0, __shfl_xor_sync(0xffffffffu, mx0, 1));
        mx0 = fmaxf(mx0, __shfl_xor_sync(0xffffffffu, mx0, 2));
        mx1 = fmaxf(mx1, __shfl_xor_sync(0xffffffffu, mx1, 1));
        mx1 = fmaxf(mx1, __shfl_xor_sync(0xffffffffu, mx1, 2));
        float mn0 = fmaxf(m0, mx0), mn1 = fmaxf(m1, mx1);
        float a0 = fast_exp2(m0 - mn0), a1 = fast_exp2(m1 - mn1);
        m0 = mn0; m1 = mn1;
#pragma unroll
        for (int f = 0; f < 8; f++) {
            o[f][0] *= a0; o[f][1] *= a0; o[f][2] *= a1; o[f][3] *= a1;
        }

        // Fused softmax + PV: per chunk kk, exp2 + cvt + 24 HMMA interleave.
        float sum0 = 0.0f, sum1 = 0.0f;
#pragma unroll
        for (int kk = 0; kk < 8; kk++) {
            float e0 = fast_exp2(s[2 * kk][0] - mn0);
            float e1 = fast_exp2(s[2 * kk][1] - mn0);
            float e2 = fast_exp2(s[2 * kk][2] - mn1);
            float e3 = fast_exp2(s[2 * kk][3] - mn1);
            float f0 = fast_exp2(s[2 * kk + 1][0] - mn0);
            float f1 = fast_exp2(s[2 * kk + 1][1] - mn0);
            float f2 = fast_exp2(s[2 * kk + 1][2] - mn1);
            float f3 = fast_exp2(s[2 * kk + 1][3] - mn1);
            sum0 += (e0 + e1) + (f0 + f1);
            sum1 += (e2 + e3) + (f2 + f3);

            uint32_t ph[4], pl[4];
            __nv_bfloat162 t0 = __floats2bfloat162_rn(e0, e1);
            __nv_bfloat162 t1 = __floats2bfloat162_rn(e2, e3);
            __nv_bfloat162 t2 = __floats2bfloat162_rn(f0, f1);
            __nv_bfloat162 t3 = __floats2bfloat162_rn(f2, f3);
            ph[0] = *(uint32_t*)&t0; ph[1] = *(uint32_t*)&t1;
            ph[2] = *(uint32_t*)&t2; ph[3] = *(uint32_t*)&t3;
            __nv_bfloat162 u0 = __floats2bfloat162_rn(e0 - __low2float(t0), e1 - __high2float(t0));
            __nv_bfloat162 u1 = __floats2bfloat162_rn(e2 - __low2float(t1), e3 - __high2float(t1));
            __nv_bfloat162 u2 = __floats2bfloat162_rn(f0 - __low2float(t2), f1 - __high2float(t2));
            __nv_bfloat162 u3 = __floats2bfloat162_rn(f2 - __low2float(t3), f3 - __high2float(t3));
            pl[0] = *(uint32_t*)&u0; pl[1] = *(uint32_t*)&u1;
            pl[2] = *(uint32_t*)&u2; pl[3] = *(uint32_t*)&u3;

#pragma unroll
            for (int dtp = 0; dtp < 4; dtp++) {
                uint32_t bh[4], bl[4];
                uint32_t off = (uint32_t)(dtp * 16 * AT_VSTR + kk * 16) * 2;
                ldsm_x4(bh, vb_h + off);
                ldsm_x4(bl, vb_l + off);
                mma_bf16(o[2 * dtp],     ph, bh);
                mma_bf16(o[2 * dtp],     ph, bl);
                mma_bf16(o[2 * dtp],     pl, bh);
                mma_bf16(o[2 * dtp + 1], ph, bh + 2);
                mma_bf16(o[2 * dtp + 1], ph, bl + 2);
                mma_bf16(o[2 * dtp + 1], pl, bh + 2);
            }
        }

        // Deferred row-sum reduction + l update (off the PV critical path)
        sum0 += __shfl_xor_sync(0xffffffffu, sum0, 1);
        sum0 += __shfl_xor_sync(0xffffffffu, sum0, 2);
        sum1 += __shfl_xor_sync(0xffffffffu, sum1, 1);
        sum1 += __shfl_xor_sync(0xffffffffu, sum1, 2);
        l0 = l0 * a0 + sum0;
        l1 = l1 * a1 + sum1;
    }
    CP_WAIT0();   // drain outstanding prefetches before exit

    // Epilogue: normalize, split to bf16 hi/lo, write ctx head-major.
    float i0 = 1.0f / l0, i1 = 1.0f / l1;
#pragma unroll
    for (int f = 0; f < 8; f++) {
        int d = f * 8 + 2 * tig;
        float v00 = o[f][0] * i0, v01 = o[f][1] * i0;
        float v10 = o[f][2] * i1, v11 = o[f][3] * i1;
        __nv_bfloat162 h0 = __floats2bfloat162_rn(v00, v01);
        __nv_bfloat162 h1 = __floats2bfloat162_rn(v10, v11);
        __nv_bfloat162 e0 = __floats2bfloat162_rn(v00 - __low2float(h0), v01 - __high2float(h0));
        __nv_bfloat162 e1 = __floats2bfloat162_rn(v10 - __low2float(h1), v11 - __high2float(h1));
        size_t b0 = (size_t)h * (N_TOK * HD) + (size_t)qrow * HD + d;
        size_t b1 = b0 + 8 * HD;
        *(__nv_bfloat162*)(g_C_hi + b0) = h0;
        *(__nv_bfloat162*)(g_C_hi + b1) = h1;
        *(__nv_bfloat162*)(g_C_lo + b0) = e0;
        *(__nv_bfloat162*)(g_C_lo + b1) = e1;
    }
}

extern "C" void kernel_launch(void* const* d_in, const int* in_sizes, int n_in,
                              void* d_out, int out_size) {
    const float* x  = (const float*)d_in[0];
    const float* Wq = (const float*)d_in[1];
    const float* Wk = (const float*)d_in[2];
    const float* Wv = (const float*)d_in[3];
    const float* Wo = (const float*)d_in[4];
    const float* bo = (const float*)d_in[5];
    float* out = (float*)d_out;

    cudaFuncSetAttribute(attn_mma, cudaFuncAttributeMaxDynamicSharedMemorySize, AT_SMEM);
    cudaFuncSetAttribute(mma_gemm, cudaFuncAttributeMaxDynamicSharedMemorySize, G_SMEM);

    split_x<<<(N_TOK * D_MODEL / 4) / 256, 256>>>(x);
    wprep<<<dim3(32, 32, 4), dim3(32, 8)>>>(Wq, Wk, Wv, Wo);
    mma_gemm<<<dim3(8, 32, 3), 256, G_SMEM>>>(0, nullptr, nullptr);
    attn_mma<<<dim3(NH, N_TOK / 128), 256, AT_SMEM>>>();
    mma_gemm<<<dim3(8, 32, 1), 256, G_SMEM>>>(1, out, bo);
}